// round 3
// baseline (speedup 1.0000x reference)
#include <cuda_runtime.h>

#define BATCH 2
#define CH 64
#define HH 224
#define WW 224
#define HW (HH*WW)           // 50176
#define NPIX (BATCH*HW)      // 100352
#define NOFF 18
#define KK 576               // 64*9
#define GEMMBLKS (NPIX/128)  // 784

typedef unsigned long long ull;

// ---------------- scratch (static device memory; no allocations) ----------------
__device__ float g_xh[NPIX*CH];      // NHWC input of current stage
__device__ float g_off[NPIX*NOFF];   // offsets NHWC
__device__ float g_xg[(size_t)NPIX*KK]; // gathered samples: xg[pix][i*64+c]
__device__ float g_yraw[NPIX*CH];    // pre-BN conv output NHWC
__device__ float g_y1n[NPIX*CH];     // stage-1 normalized output NHWC
__device__ float g_Wt1[KK*CH];       // Wt[(i*64+c)*64+o] = w_conv[o][c*9+i]
__device__ float g_Wt2[KK*CH];
__device__ float g_sp[GEMMBLKS*CH];  // partial sums (one row per gemm block)
__device__ float g_qp[GEMMBLKS*CH];  // partial sumsq
__device__ float g_ab[2*CH];         // per-channel scale a, shift b

#define FMA2(acc, w, x) asm("fma.rn.f32x2 %0, %1, %2, %0;" : "+l"(acc) : "l"(w), "l"(x))

// ---------------- NCHW -> NHWC transpose ----------------
__global__ __launch_bounds__(256) void k_nchw2nhwc(const float* __restrict__ x) {
    __shared__ float tile[32][33];
    int b = blockIdx.z;
    int s0 = blockIdx.x * 32, c0 = blockIdx.y * 32;
    int tx = threadIdx.x, ty = threadIdx.y;
#pragma unroll
    for (int j = 0; j < 4; j++) {
        int c = c0 + ty + j*8;
        tile[ty + j*8][tx] = x[(b*CH + c)*HW + s0 + tx];
    }
    __syncthreads();
#pragma unroll
    for (int j = 0; j < 4; j++) {
        int s = s0 + ty + j*8;
        g_xh[(b*HW + s)*CH + c0 + tx] = tile[tx][ty + j*8];
    }
}

// ---------------- W prep: dst[(i*64+c)*64 + o] = wconv[o][c*9+i] ----------------
__global__ void k_prepwt(const float* __restrict__ wconv, float* __restrict__ dst) {
    int j = blockIdx.x * 256 + threadIdx.x;
    if (j < KK*CH) {
        int o = j & 63;
        int k = j >> 6;       // k = i*64 + c
        int i = k >> 6;
        int c = k & 63;
        dst[j] = wconv[o*KK + c*9 + i];
    }
}

// ---------------- offset conv: 3x3, pad 1, 64->18 channels ----------------
#define OFF_SMEM ((10376 + 64*204) * 4)
__global__ __launch_bounds__(160) void k_offconv(const float* __restrict__ in,
                                                 const float* __restrict__ woff,
                                                 const float* __restrict__ boff) {
    extern __shared__ float sm[];
    float* Ws = sm;              // 10368 floats
    float* patch = sm + 10376;   // 64*204 floats
    int t = threadIdx.x;
    int w0 = blockIdx.x * 64, h = blockIdx.y, b = blockIdx.z;

    for (int j = t; j < NOFF*KK; j += 160) Ws[j] = woff[j];
    for (int j = t; j < 3*66*64; j += 160) {
        int c = j & 63; int r = j >> 6; int p = r % 66; int kx = r / 66;
        int hr = h - 1 + kx; int wc = w0 - 1 + p;
        float v = 0.f;
        if ((unsigned)hr < (unsigned)HH && (unsigned)wc < (unsigned)WW)
            v = in[((b*HH + hr)*WW + wc)*CH + c];
        patch[c*204 + kx*68 + p] = v;
    }
    __syncthreads();

    if (t < 144) {
        int og = t >> 4;
        int pl = t & 15;
        float acc0[4] = {0,0,0,0};
        float acc1[4] = {0,0,0,0};
        for (int c = 0; c < CH; c++) {
#pragma unroll
            for (int kx = 0; kx < 3; kx++) {
                const float* pr = patch + c*204 + kx*68 + pl*4;
                float4 f4 = *(const float4*)pr;
                float2 f2 = *(const float2*)(pr + 4);
                float pv[6] = {f4.x, f4.y, f4.z, f4.w, f2.x, f2.y};
                const float* wb0 = Ws + og*KK + c*9 + kx*3;
                const float* wb1 = Ws + (og+9)*KK + c*9 + kx*3;
#pragma unroll
                for (int ky = 0; ky < 3; ky++) {
                    float wa = wb0[ky], wb = wb1[ky];
#pragma unroll
                    for (int pp = 0; pp < 4; pp++) {
                        acc0[pp] = fmaf(wa, pv[ky+pp], acc0[pp]);
                        acc1[pp] = fmaf(wb, pv[ky+pp], acc1[pp]);
                    }
                }
            }
        }
        float bi0 = boff[og], bi1 = boff[og+9];
#pragma unroll
        for (int pp = 0; pp < 4; pp++) {
            int w = w0 + pl*4 + pp;
            if (w < WW) {
                int base = ((b*HH + h)*WW + w)*NOFF;
                g_off[base + og]     = acc0[pp] + bi0;
                g_off[base + og + 9] = acc1[pp] + bi1;
            }
        }
    }
}

// ---------------- gather: bilinear sample -> g_xg[pix][i*64+c] ----------------
// 32 pixels/block. float4 channel lanes: 16 lanes per descriptor, 2 desc/warp.
__global__ __launch_bounds__(256) void k_gather(const float* __restrict__ in,
                                                float* __restrict__ xg) {
    __shared__ int4   gA[288];
    __shared__ float4 gW[288];
    __shared__ int    gO[288];
    int t = threadIdx.x;
    int pix0 = blockIdx.x * 32;
    int b = pix0 / HW; int hw = pix0 - b*HW;
    int h = hw / WW;  int w0 = hw - h*WW;

    for (int j = t; j < 288; j += 256) {
        int p = j / 9; int i = j - p*9;
        int pix = pix0 + p;
        float ox = g_off[pix*NOFF + i];
        float oy = g_off[pix*NOFF + 9 + i];
        float px = (float)(h + (i/3)) + ox;
        float py = (float)(w0 + p + (i%3)) + oy;
        float fx = floorf(px), fy = floorf(py);
        int x0 = (int)fx, y0 = (int)fy;
        int x1 = x0 + 1, y1 = y0 + 1;
        x0 = min(max(x0, 0), HH-1); x1 = min(max(x1, 0), HH-1);
        y0 = min(max(y0, 0), WW-1); y1 = min(max(y1, 0), WW-1);
        float pxc = fminf(fmaxf(px, 0.f), (float)(HH-1));
        float pyc = fminf(fmaxf(py, 0.f), (float)(WW-1));
        float wx0 = 1.f + (float)x0 - pxc;
        float wx1 = 1.f - (float)x1 + pxc;
        float wy0 = 1.f + (float)y0 - pyc;
        float wy1 = 1.f - (float)y1 + pyc;
        int base = b * HW;
        gA[j] = make_int4((base + x0*WW + y0)*CH, (base + x1*WW + y1)*CH,
                          (base + x0*WW + y1)*CH, (base + x1*WW + y0)*CH);
        gW[j] = make_float4(wx0*wy0, wx1*wy1, wx0*wy1, wx1*wy0);
        gO[j] = pix*KK + i*64;
    }
    __syncthreads();

    int c4 = (t & 15) * 4;
    int d0 = t >> 4;                 // group id 0..15
#pragma unroll 3
    for (int it = 0; it < 18; it++) {
        int desc = d0 + it*16;
        int4 a = gA[desc]; float4 g = gW[desc];
        float4 v0 = *(const float4*)(in + a.x + c4);
        float4 v1 = *(const float4*)(in + a.y + c4);
        float4 v2 = *(const float4*)(in + a.z + c4);
        float4 v3 = *(const float4*)(in + a.w + c4);
        float4 r;
        r.x = fmaf(g.w, v3.x, fmaf(g.z, v2.x, fmaf(g.y, v1.x, g.x*v0.x)));
        r.y = fmaf(g.w, v3.y, fmaf(g.z, v2.y, fmaf(g.y, v1.y, g.x*v0.y)));
        r.z = fmaf(g.w, v3.z, fmaf(g.z, v2.z, fmaf(g.y, v1.z, g.x*v0.z)));
        r.w = fmaf(g.w, v3.w, fmaf(g.z, v2.w, fmaf(g.y, v1.w, g.x*v0.w)));
        *(float4*)(xg + gO[desc] + c4) = r;
    }
}

// ---------------- GEMM + fused BN partial stats ----------------
// 128 pix x 64 och per block, 256 threads, k-chunks of 32, f32x2 packed math.
__global__ __launch_bounds__(256, 3) void k_gemm(const float* __restrict__ xg,
                                                 const float* __restrict__ wt,
                                                 float* __restrict__ yout) {
    __shared__ float Xs[32*128];    // XOR-swizzled: [row k][phys col]
    __shared__ float Ws[32*64];
    int t = threadIdx.x;
    int pix0 = blockIdx.x * 128;
    int og = t & 15, pg = t >> 4;

    float4 xr[4]; float4 wr[2];

    // prefetch chunk 0
#pragma unroll
    for (int l = 0; l < 4; l++) {
        int idx = t + 256*l; int p = idx >> 3, kq = idx & 7;
        xr[l] = *(const float4*)(xg + (size_t)(pix0+p)*KK + kq*4);
    }
#pragma unroll
    for (int l = 0; l < 2; l++) {
        int idx = t + 256*l; int row = idx >> 4, q = idx & 15;
        wr[l] = *(const float4*)(wt + row*64 + q*4);
    }

    ull acc[4][4];
#pragma unroll
    for (int a = 0; a < 4; a++)
#pragma unroll
        for (int q = 0; q < 4; q++) acc[a][q] = 0ull;

    for (int kc = 0; kc < 18; kc++) {
        __syncthreads();
#pragma unroll
        for (int l = 0; l < 4; l++) {
            int idx = t + 256*l; int p = idx >> 3, kq = idx & 7;
#pragma unroll
            for (int j = 0; j < 4; j++) {
                int row = kq*4 + j;
                Xs[row*128 + (((p>>2) ^ kq) << 2) + (p & 3)] = (&xr[l].x)[j];
            }
        }
#pragma unroll
        for (int l = 0; l < 2; l++) {
            int idx = t + 256*l; int row = idx >> 4, q = idx & 15;
            *(float4*)(Ws + row*64 + q*4) = wr[l];
        }
        __syncthreads();

        if (kc < 17) {
            int k0 = (kc+1)*32;
#pragma unroll
            for (int l = 0; l < 4; l++) {
                int idx = t + 256*l; int p = idx >> 3, kq = idx & 7;
                xr[l] = *(const float4*)(xg + (size_t)(pix0+p)*KK + k0 + kq*4);
            }
#pragma unroll
            for (int l = 0; l < 2; l++) {
                int idx = t + 256*l; int row = idx >> 4, q = idx & 15;
                wr[l] = *(const float4*)(wt + (k0+row)*64 + q*4);
            }
        }

#pragma unroll
        for (int kk = 0; kk < 32; kk++) {
            float4 wv = *(const float4*)(Ws + kk*64 + og*4);
            int s = kk >> 2;
            const float* xrow = Xs + kk*128;
            int uA = (((pg*2)   ^ s) << 2);
            int uB = (((pg*2+1) ^ s) << 2);
            ull x0 = *(const ull*)(xrow + uA);
            ull x1 = *(const ull*)(xrow + uA + 2);
            ull x2 = *(const ull*)(xrow + uB);
            ull x3 = *(const ull*)(xrow + uB + 2);
#pragma unroll
            for (int a = 0; a < 4; a++) {
                float wa = (&wv.x)[a];
                ull w2;
                asm("mov.b64 %0, {%1, %1};" : "=l"(w2) : "f"(wa));
                FMA2(acc[a][0], w2, x0);
                FMA2(acc[a][1], w2, x1);
                FMA2(acc[a][2], w2, x2);
                FMA2(acc[a][3], w2, x3);
            }
        }
    }

    // epilogue: unpack pairs, write NHWC, accumulate per-channel stats
    float s4[4] = {0,0,0,0}, q4[4] = {0,0,0,0};
#pragma unroll
    for (int q = 0; q < 4; q++) {
        float lo[4], hi[4];
#pragma unroll
        for (int a = 0; a < 4; a++) {
            asm("mov.b64 {%0, %1}, %2;" : "=f"(lo[a]), "=f"(hi[a]) : "l"(acc[a][q]));
            s4[a] += lo[a] + hi[a];
            q4[a] = fmaf(lo[a], lo[a], q4[a]);
            q4[a] = fmaf(hi[a], hi[a], q4[a]);
        }
        int p = pix0 + pg*8 + 2*q;
        *(float4*)(yout + (size_t)p*CH + og*4)     = make_float4(lo[0], lo[1], lo[2], lo[3]);
        *(float4*)(yout + (size_t)(p+1)*CH + og*4) = make_float4(hi[0], hi[1], hi[2], hi[3]);
    }
    __syncthreads();
    *(float4*)(Xs + pg*64 + og*4) = make_float4(s4[0], s4[1], s4[2], s4[3]);
    *(float4*)(Ws + pg*64 + og*4) = make_float4(q4[0], q4[1], q4[2], q4[3]);
    __syncthreads();
    if (t < 64) {
        float s = 0.f, qq = 0.f;
#pragma unroll
        for (int g = 0; g < 16; g++) { s += Xs[g*64 + t]; qq += Ws[g*64 + t]; }
        g_sp[blockIdx.x*64 + t] = s;
        g_qp[blockIdx.x*64 + t] = qq;
    }
}

// ---------------- BN finish: reduce 784 partials ----------------
__global__ __launch_bounds__(256) void k_bnfinish(const float* __restrict__ gamma,
                                                  const float* __restrict__ beta) {
    __shared__ float ss[256], sq[256];
    int t = threadIdx.x;
    int c = t & 63, sub = t >> 6;
    float s = 0.f, q = 0.f;
    for (int i = sub; i < GEMMBLKS; i += 4) {
        s += g_sp[i*64 + c];
        q += g_qp[i*64 + c];
    }
    ss[t] = s; sq[t] = q;
    __syncthreads();
    if (t < 64) {
        s = ss[t] + ss[t+64] + ss[t+128] + ss[t+192];
        q = sq[t] + sq[t+64] + sq[t+128] + sq[t+192];
        float inv = 1.f / (float)NPIX;
        float mean = s * inv;
        float var = fmaxf(q * inv - mean*mean, 0.f);
        float r = rsqrtf(var + 1e-5f);
        float a = gamma[t] * r;
        g_ab[t] = a;
        g_ab[64 + t] = beta[t] - mean * a;
    }
}

// ---------------- BN apply + relu, NHWC -> NHWC (stage-1 output) ----------------
__global__ __launch_bounds__(256) void k_bnapply_nhwc(const float* __restrict__ y) {
    int v = blockIdx.x * 256 + threadIdx.x;
    float4 t4 = ((const float4*)y)[v];
    int c = (v & 15) * 4;
    float4 r;
    r.x = fmaxf(fmaf(t4.x, g_ab[c+0], g_ab[64+c+0]), 0.f);
    r.y = fmaxf(fmaf(t4.y, g_ab[c+1], g_ab[64+c+1]), 0.f);
    r.z = fmaxf(fmaf(t4.z, g_ab[c+2], g_ab[64+c+2]), 0.f);
    r.w = fmaxf(fmaf(t4.w, g_ab[c+3], g_ab[64+c+3]), 0.f);
    ((float4*)g_y1n)[v] = r;
}

// ---------------- BN apply + relu + NHWC -> NCHW (final output) ----------------
__global__ __launch_bounds__(256) void k_bnapply_nchw(const float* __restrict__ y,
                                                      float* __restrict__ out) {
    __shared__ float tile[64*33];
    int t = threadIdx.x;
    int pix0 = blockIdx.x * 32;
    int b = pix0 / HW, hw0 = pix0 - b*HW;
    int c = t & 63, q = t >> 6;
    float a = g_ab[c], bb = g_ab[64 + c];
#pragma unroll
    for (int j = 0; j < 8; j++) {
        int p = q*8 + j;
        float v = y[(pix0 + p)*CH + c];
        tile[c*33 + p] = fmaxf(fmaf(v, a, bb), 0.f);
    }
    __syncthreads();
    int p2 = t & 31, cq = t >> 5;
#pragma unroll
    for (int j = 0; j < 8; j++) {
        int cc = cq*8 + j;
        out[(b*CH + cc)*HW + hw0 + p2] = tile[cc*33 + p2];
    }
}

// ---------------- launch ----------------
extern "C" void kernel_launch(void* const* d_in, const int* in_sizes, int n_in,
                              void* d_out, int out_size) {
    const float* x      = (const float*)d_in[0];
    const float* woff1  = (const float*)d_in[1];
    const float* boff1  = (const float*)d_in[2];
    const float* wconv1 = (const float*)d_in[3];
    const float* gamma1 = (const float*)d_in[4];
    const float* beta1  = (const float*)d_in[5];
    const float* woff2  = (const float*)d_in[6];
    const float* boff2  = (const float*)d_in[7];
    const float* wconv2 = (const float*)d_in[8];
    const float* gamma2 = (const float*)d_in[9];
    const float* beta2  = (const float*)d_in[10];
    float* out = (float*)d_out;

    float *p_xh, *p_y1n, *p_yraw, *p_xg, *p_wt1, *p_wt2;
    cudaGetSymbolAddress((void**)&p_xh,   g_xh);
    cudaGetSymbolAddress((void**)&p_y1n,  g_y1n);
    cudaGetSymbolAddress((void**)&p_yraw, g_yraw);
    cudaGetSymbolAddress((void**)&p_xg,   g_xg);
    cudaGetSymbolAddress((void**)&p_wt1,  g_Wt1);
    cudaGetSymbolAddress((void**)&p_wt2,  g_Wt2);

    cudaFuncSetAttribute(k_offconv, cudaFuncAttributeMaxDynamicSharedMemorySize, OFF_SMEM);

    // stage 1  (launch order keeps k_gemm at ncu capture slot 6: -s 5 -c 1)
    k_nchw2nhwc<<<dim3(HW/32, 2, BATCH), dim3(32, 8)>>>(x);                    // 1
    k_prepwt<<<144, 256>>>(wconv1, p_wt1);                                     // 2
    k_prepwt<<<144, 256>>>(wconv2, p_wt2);                                     // 3
    k_offconv<<<dim3(4, HH, BATCH), 160, OFF_SMEM>>>(p_xh, woff1, boff1);      // 4
    k_gather<<<NPIX/32, 256>>>(p_xh, p_xg);                                    // 5
    k_gemm<<<GEMMBLKS, 256>>>(p_xg, p_wt1, p_yraw);                            // 6
    k_bnfinish<<<1, 256>>>(gamma1, beta1);                                     // 7
    k_bnapply_nhwc<<<NPIX*CH/4/256, 256>>>(p_yraw);                            // 8

    // stage 2
    k_offconv<<<dim3(4, HH, BATCH), 160, OFF_SMEM>>>(p_y1n, woff2, boff2);     // 9
    k_gather<<<NPIX/32, 256>>>(p_y1n, p_xg);                                   // 10
    k_gemm<<<GEMMBLKS, 256>>>(p_xg, p_wt2, p_yraw);                            // 11
    k_bnfinish<<<1, 256>>>(gamma2, beta2);                                     // 12
    k_bnapply_nchw<<<NPIX/32, 256>>>(p_yraw, out);                             // 13
}

// round 4
// speedup vs baseline: 1.1061x; 1.1061x over previous
#include <cuda_runtime.h>

#define BATCH 2
#define CH 64
#define HH 224
#define WW 224
#define HW (HH*WW)           // 50176
#define NPIX (BATCH*HW)      // 100352
#define NOFF 18
#define KK 576               // 64*9
#define GEMMBLKS (NPIX/128)  // 784

typedef unsigned long long ull;

// ---------------- scratch (static device memory; no allocations) ----------------
__device__ float g_xh[NPIX*CH];      // NHWC input of current stage
__device__ float g_off[NPIX*NOFF];   // offsets NHWC
__device__ float g_xg[(size_t)NPIX*KK]; // gathered samples: xg[pix][i*64+c]
__device__ float g_yraw[NPIX*CH];    // pre-BN conv output NHWC
__device__ float g_y1n[NPIX*CH];     // stage-1 normalized output NHWC
__device__ float g_Wt1[KK*CH];       // Wt[(i*64+c)*64+o] = w_conv[o][c*9+i]
__device__ float g_Wt2[KK*CH];
__device__ float g_sp[GEMMBLKS*CH];  // partial sums (one row per gemm block)
__device__ float g_qp[GEMMBLKS*CH];  // partial sumsq
__device__ float g_ab[2*CH];         // per-channel scale a, shift b

#define FMA2(acc, w, x) asm("fma.rn.f32x2 %0, %1, %2, %0;" : "+l"(acc) : "l"(w), "l"(x))

// ---------------- NCHW -> NHWC transpose ----------------
__global__ __launch_bounds__(256) void k_nchw2nhwc(const float* __restrict__ x) {
    __shared__ float tile[32][33];
    int b = blockIdx.z;
    int s0 = blockIdx.x * 32, c0 = blockIdx.y * 32;
    int tx = threadIdx.x, ty = threadIdx.y;
#pragma unroll
    for (int j = 0; j < 4; j++) {
        int c = c0 + ty + j*8;
        tile[ty + j*8][tx] = x[(b*CH + c)*HW + s0 + tx];
    }
    __syncthreads();
#pragma unroll
    for (int j = 0; j < 4; j++) {
        int s = s0 + ty + j*8;
        g_xh[(b*HW + s)*CH + c0 + tx] = tile[tx][ty + j*8];
    }
}

// ---------------- W prep: dst[(i*64+c)*64 + o] = wconv[o][c*9+i] ----------------
__global__ void k_prepwt(const float* __restrict__ wconv, float* __restrict__ dst) {
    int j = blockIdx.x * 256 + threadIdx.x;
    if (j < KK*CH) {
        int o = j & 63;
        int k = j >> 6;       // k = i*64 + c
        int i = k >> 6;
        int c = k & 63;
        dst[j] = wconv[o*KK + c*9 + i];
    }
}

// ---------------- offset conv: 3x3, pad 1, 64->18 ch, f32x2 og-pair packed ----
// Block 288 threads: warp = og-pair (og, og+9), lane = 2 pixels of 64-wide tile.
#define OFF_SMEM ((10368 + 13056) * 4)
__global__ __launch_bounds__(288, 2) void k_offconv(const float* __restrict__ in,
                                                    const float* __restrict__ woff,
                                                    const float* __restrict__ boff) {
    extern __shared__ float sm[];
    float* sW = sm;            // [c][tap][og9][2] : 10368 floats (paired weights)
    float* patch = sm + 10368; // [c][kx][68] : 13056 floats (66 used per row)
    int t = threadIdx.x;
    int w0 = blockIdx.x * 64, h = blockIdx.y, b = blockIdx.z;

    // paired weight fill: sW[((c*9+tap)*9+og9)*2+hh] = woff[(og9+hh*9)*576 + c*9+tap]
    for (int j = t; j < 10368; j += 288) {
        int hh = j & 1; int r = j >> 1;
        int og9 = r % 9; int ct = r / 9;
        int tap = ct % 9; int c = ct / 9;
        sW[j] = woff[(og9 + hh*9)*KK + c*9 + tap];
    }
    // input patch: rows h-1..h+1, cols w0-1..w0+64, zero-padded
    for (int j = t; j < 3*66*64; j += 288) {
        int c = j & 63; int r = j >> 6; int p = r % 66; int kx = r / 66;
        int hr = h - 1 + kx; int wc = w0 - 1 + p;
        float v = 0.f;
        if ((unsigned)hr < (unsigned)HH && (unsigned)wc < (unsigned)WW)
            v = in[((b*HH + hr)*WW + wc)*CH + c];
        patch[c*204 + kx*68 + p] = v;
    }
    __syncthreads();

    int wid = t >> 5, lane = t & 31;
    int p = lane * 2;
    ull acc0 = 0ull, acc1 = 0ull;   // (out[wid], out[wid+9]) for px0, px1
    for (int c = 0; c < CH; c++) {
        const float* pr = patch + c*204;
        const float* wp = sW + c*162 + wid*2;
#pragma unroll
        for (int kx = 0; kx < 3; kx++) {
            float2 ab = *(const float2*)(pr + kx*68 + p);
            float2 cd = *(const float2*)(pr + kx*68 + p + 2);
            ull d0, d1, d2, d3;
            asm("mov.b64 %0,{%1,%1};" : "=l"(d0) : "f"(ab.x));
            asm("mov.b64 %0,{%1,%1};" : "=l"(d1) : "f"(ab.y));
            asm("mov.b64 %0,{%1,%1};" : "=l"(d2) : "f"(cd.x));
            asm("mov.b64 %0,{%1,%1};" : "=l"(d3) : "f"(cd.y));
            ull w2a = *(const ull*)(wp + (kx*3+0)*18);
            ull w2b = *(const ull*)(wp + (kx*3+1)*18);
            ull w2c = *(const ull*)(wp + (kx*3+2)*18);
            FMA2(acc0, w2a, d0); FMA2(acc1, w2a, d1);
            FMA2(acc0, w2b, d1); FMA2(acc1, w2b, d2);
            FMA2(acc0, w2c, d2); FMA2(acc1, w2c, d3);
        }
    }
    float b0 = boff[wid], b9 = boff[wid+9];
    float lo0, hi0, lo1, hi1;
    asm("mov.b64 {%0,%1}, %2;" : "=f"(lo0), "=f"(hi0) : "l"(acc0));
    asm("mov.b64 {%0,%1}, %2;" : "=f"(lo1), "=f"(hi1) : "l"(acc1));
    int w = w0 + p;
    if (w < WW) {
        int base = ((b*HH + h)*WW + w)*NOFF;
        g_off[base + wid]     = lo0 + b0;
        g_off[base + wid + 9] = hi0 + b9;
    }
    if (w + 1 < WW) {
        int base = ((b*HH + h)*WW + w + 1)*NOFF;
        g_off[base + wid]     = lo1 + b0;
        g_off[base + wid + 9] = hi1 + b9;
    }
}

// ---------------- gather: bilinear sample -> g_xg[pix][i*64+c] ----------------
__global__ __launch_bounds__(256) void k_gather(const float* __restrict__ in,
                                                float* __restrict__ xg) {
    __shared__ int4   gA[288];
    __shared__ float4 gW[288];
    __shared__ int    gO[288];
    int t = threadIdx.x;
    int pix0 = blockIdx.x * 32;
    int b = pix0 / HW; int hw = pix0 - b*HW;
    int h = hw / WW;  int w0 = hw - h*WW;

    for (int j = t; j < 288; j += 256) {
        int p = j / 9; int i = j - p*9;
        int pix = pix0 + p;
        float ox = g_off[pix*NOFF + i];
        float oy = g_off[pix*NOFF + 9 + i];
        float px = (float)(h + (i/3)) + ox;
        float py = (float)(w0 + p + (i%3)) + oy;
        float fx = floorf(px), fy = floorf(py);
        int x0 = (int)fx, y0 = (int)fy;
        int x1 = x0 + 1, y1 = y0 + 1;
        x0 = min(max(x0, 0), HH-1); x1 = min(max(x1, 0), HH-1);
        y0 = min(max(y0, 0), WW-1); y1 = min(max(y1, 0), WW-1);
        float pxc = fminf(fmaxf(px, 0.f), (float)(HH-1));
        float pyc = fminf(fmaxf(py, 0.f), (float)(WW-1));
        float wx0 = 1.f + (float)x0 - pxc;
        float wx1 = 1.f - (float)x1 + pxc;
        float wy0 = 1.f + (float)y0 - pyc;
        float wy1 = 1.f - (float)y1 + pyc;
        int base = b * HW;
        gA[j] = make_int4((base + x0*WW + y0)*CH, (base + x1*WW + y1)*CH,
                          (base + x0*WW + y1)*CH, (base + x1*WW + y0)*CH);
        gW[j] = make_float4(wx0*wy0, wx1*wy1, wx0*wy1, wx1*wy0);
        gO[j] = pix*KK + i*64;
    }
    __syncthreads();

    int c4 = (t & 15) * 4;
    int d0 = t >> 4;                 // group id 0..15
#pragma unroll 3
    for (int it = 0; it < 18; it++) {
        int desc = d0 + it*16;
        int4 a = gA[desc]; float4 g = gW[desc];
        float4 v0 = *(const float4*)(in + a.x + c4);
        float4 v1 = *(const float4*)(in + a.y + c4);
        float4 v2 = *(const float4*)(in + a.z + c4);
        float4 v3 = *(const float4*)(in + a.w + c4);
        float4 r;
        r.x = fmaf(g.w, v3.x, fmaf(g.z, v2.x, fmaf(g.y, v1.x, g.x*v0.x)));
        r.y = fmaf(g.w, v3.y, fmaf(g.z, v2.y, fmaf(g.y, v1.y, g.x*v0.y)));
        r.z = fmaf(g.w, v3.z, fmaf(g.z, v2.z, fmaf(g.y, v1.z, g.x*v0.z)));
        r.w = fmaf(g.w, v3.w, fmaf(g.z, v2.w, fmaf(g.y, v1.w, g.x*v0.w)));
        *(float4*)(xg + gO[desc] + c4) = r;
    }
}

// ---------------- GEMM + fused BN partial stats ----------------
__global__ __launch_bounds__(256, 3) void k_gemm(const float* __restrict__ xg,
                                                 const float* __restrict__ wt,
                                                 float* __restrict__ yout) {
    __shared__ float Xs[32*128];    // XOR-swizzled: [row k][phys col]
    __shared__ float Ws[32*64];
    int t = threadIdx.x;
    int pix0 = blockIdx.x * 128;
    int og = t & 15, pg = t >> 4;

    float4 xr[4]; float4 wr[2];

#pragma unroll
    for (int l = 0; l < 4; l++) {
        int idx = t + 256*l; int p = idx >> 3, kq = idx & 7;
        xr[l] = *(const float4*)(xg + (size_t)(pix0+p)*KK + kq*4);
    }
#pragma unroll
    for (int l = 0; l < 2; l++) {
        int idx = t + 256*l; int row = idx >> 4, q = idx & 15;
        wr[l] = *(const float4*)(wt + row*64 + q*4);
    }

    ull acc[4][4];
#pragma unroll
    for (int a = 0; a < 4; a++)
#pragma unroll
        for (int q = 0; q < 4; q++) acc[a][q] = 0ull;

    for (int kc = 0; kc < 18; kc++) {
        __syncthreads();
#pragma unroll
        for (int l = 0; l < 4; l++) {
            int idx = t + 256*l; int p = idx >> 3, kq = idx & 7;
#pragma unroll
            for (int j = 0; j < 4; j++) {
                int row = kq*4 + j;
                Xs[row*128 + (((p>>2) ^ kq) << 2) + (p & 3)] = (&xr[l].x)[j];
            }
        }
#pragma unroll
        for (int l = 0; l < 2; l++) {
            int idx = t + 256*l; int row = idx >> 4, q = idx & 15;
            *(float4*)(Ws + row*64 + q*4) = wr[l];
        }
        __syncthreads();

        if (kc < 17) {
            int k0 = (kc+1)*32;
#pragma unroll
            for (int l = 0; l < 4; l++) {
                int idx = t + 256*l; int p = idx >> 3, kq = idx & 7;
                xr[l] = *(const float4*)(xg + (size_t)(pix0+p)*KK + k0 + kq*4);
            }
#pragma unroll
            for (int l = 0; l < 2; l++) {
                int idx = t + 256*l; int row = idx >> 4, q = idx & 15;
                wr[l] = *(const float4*)(wt + (k0+row)*64 + q*4);
            }
        }

#pragma unroll
        for (int kk = 0; kk < 32; kk++) {
            float4 wv = *(const float4*)(Ws + kk*64 + og*4);
            int s = kk >> 2;
            const float* xrow = Xs + kk*128;
            int uA = (((pg*2)   ^ s) << 2);
            int uB = (((pg*2+1) ^ s) << 2);
            ull x0 = *(const ull*)(xrow + uA);
            ull x1 = *(const ull*)(xrow + uA + 2);
            ull x2 = *(const ull*)(xrow + uB);
            ull x3 = *(const ull*)(xrow + uB + 2);
#pragma unroll
            for (int a = 0; a < 4; a++) {
                float wa = (&wv.x)[a];
                ull w2;
                asm("mov.b64 %0, {%1, %1};" : "=l"(w2) : "f"(wa));
                FMA2(acc[a][0], w2, x0);
                FMA2(acc[a][1], w2, x1);
                FMA2(acc[a][2], w2, x2);
                FMA2(acc[a][3], w2, x3);
            }
        }
    }

    float s4[4] = {0,0,0,0}, q4[4] = {0,0,0,0};
#pragma unroll
    for (int q = 0; q < 4; q++) {
        float lo[4], hi[4];
#pragma unroll
        for (int a = 0; a < 4; a++) {
            asm("mov.b64 {%0, %1}, %2;" : "=f"(lo[a]), "=f"(hi[a]) : "l"(acc[a][q]));
            s4[a] += lo[a] + hi[a];
            q4[a] = fmaf(lo[a], lo[a], q4[a]);
            q4[a] = fmaf(hi[a], hi[a], q4[a]);
        }
        int p = pix0 + pg*8 + 2*q;
        *(float4*)(yout + (size_t)p*CH + og*4)     = make_float4(lo[0], lo[1], lo[2], lo[3]);
        *(float4*)(yout + (size_t)(p+1)*CH + og*4) = make_float4(hi[0], hi[1], hi[2], hi[3]);
    }
    __syncthreads();
    *(float4*)(Xs + pg*64 + og*4) = make_float4(s4[0], s4[1], s4[2], s4[3]);
    *(float4*)(Ws + pg*64 + og*4) = make_float4(q4[0], q4[1], q4[2], q4[3]);
    __syncthreads();
    if (t < 64) {
        float s = 0.f, qq = 0.f;
#pragma unroll
        for (int g = 0; g < 16; g++) { s += Xs[g*64 + t]; qq += Ws[g*64 + t]; }
        g_sp[blockIdx.x*64 + t] = s;
        g_qp[blockIdx.x*64 + t] = qq;
    }
}

// ---------------- BN finish: reduce 784 partials ----------------
__global__ __launch_bounds__(256) void k_bnfinish(const float* __restrict__ gamma,
                                                  const float* __restrict__ beta) {
    __shared__ float ss[256], sq[256];
    int t = threadIdx.x;
    int c = t & 63, sub = t >> 6;
    float s = 0.f, q = 0.f;
    for (int i = sub; i < GEMMBLKS; i += 4) {
        s += g_sp[i*64 + c];
        q += g_qp[i*64 + c];
    }
    ss[t] = s; sq[t] = q;
    __syncthreads();
    if (t < 64) {
        s = ss[t] + ss[t+64] + ss[t+128] + ss[t+192];
        q = sq[t] + sq[t+64] + sq[t+128] + sq[t+192];
        float inv = 1.f / (float)NPIX;
        float mean = s * inv;
        float var = fmaxf(q * inv - mean*mean, 0.f);
        float r = rsqrtf(var + 1e-5f);
        float a = gamma[t] * r;
        g_ab[t] = a;
        g_ab[64 + t] = beta[t] - mean * a;
    }
}

// ---------------- BN apply + relu, NHWC -> NHWC (stage-1 output) ----------------
__global__ __launch_bounds__(256) void k_bnapply_nhwc(const float* __restrict__ y) {
    int v = blockIdx.x * 256 + threadIdx.x;
    float4 t4 = ((const float4*)y)[v];
    int c = (v & 15) * 4;
    float4 r;
    r.x = fmaxf(fmaf(t4.x, g_ab[c+0], g_ab[64+c+0]), 0.f);
    r.y = fmaxf(fmaf(t4.y, g_ab[c+1], g_ab[64+c+1]), 0.f);
    r.z = fmaxf(fmaf(t4.z, g_ab[c+2], g_ab[64+c+2]), 0.f);
    r.w = fmaxf(fmaf(t4.w, g_ab[c+3], g_ab[64+c+3]), 0.f);
    ((float4*)g_y1n)[v] = r;
}

// ---------------- BN apply + relu + NHWC -> NCHW (final output) ----------------
__global__ __launch_bounds__(256) void k_bnapply_nchw(const float* __restrict__ y,
                                                      float* __restrict__ out) {
    __shared__ float tile[64*33];
    int t = threadIdx.x;
    int pix0 = blockIdx.x * 32;
    int b = pix0 / HW, hw0 = pix0 - b*HW;
    int c = t & 63, q = t >> 6;
    float a = g_ab[c], bb = g_ab[64 + c];
#pragma unroll
    for (int j = 0; j < 8; j++) {
        int p = q*8 + j;
        float v = y[(pix0 + p)*CH + c];
        tile[c*33 + p] = fmaxf(fmaf(v, a, bb), 0.f);
    }
    __syncthreads();
    int p2 = t & 31, cq = t >> 5;
#pragma unroll
    for (int j = 0; j < 8; j++) {
        int cc = cq*8 + j;
        out[(b*CH + cc)*HW + hw0 + p2] = tile[cc*33 + p2];
    }
}

// ---------------- launch ----------------
extern "C" void kernel_launch(void* const* d_in, const int* in_sizes, int n_in,
                              void* d_out, int out_size) {
    const float* x      = (const float*)d_in[0];
    const float* woff1  = (const float*)d_in[1];
    const float* boff1  = (const float*)d_in[2];
    const float* wconv1 = (const float*)d_in[3];
    const float* gamma1 = (const float*)d_in[4];
    const float* beta1  = (const float*)d_in[5];
    const float* woff2  = (const float*)d_in[6];
    const float* boff2  = (const float*)d_in[7];
    const float* wconv2 = (const float*)d_in[8];
    const float* gamma2 = (const float*)d_in[9];
    const float* beta2  = (const float*)d_in[10];
    float* out = (float*)d_out;

    float *p_xh, *p_y1n, *p_yraw, *p_xg, *p_wt1, *p_wt2;
    cudaGetSymbolAddress((void**)&p_xh,   g_xh);
    cudaGetSymbolAddress((void**)&p_y1n,  g_y1n);
    cudaGetSymbolAddress((void**)&p_yraw, g_yraw);
    cudaGetSymbolAddress((void**)&p_xg,   g_xg);
    cudaGetSymbolAddress((void**)&p_wt1,  g_Wt1);
    cudaGetSymbolAddress((void**)&p_wt2,  g_Wt2);

    cudaFuncSetAttribute(k_offconv, cudaFuncAttributeMaxDynamicSharedMemorySize, OFF_SMEM);

    // stage 1  (k_gemm stays at ncu capture slot 6: -s 5 -c 1)
    k_nchw2nhwc<<<dim3(HW/32, 2, BATCH), dim3(32, 8)>>>(x);                    // 1
    k_prepwt<<<144, 256>>>(wconv1, p_wt1);                                     // 2
    k_prepwt<<<144, 256>>>(wconv2, p_wt2);                                     // 3
    k_offconv<<<dim3(4, HH, BATCH), 288, OFF_SMEM>>>(p_xh, woff1, boff1);      // 4
    k_gather<<<NPIX/32, 256>>>(p_xh, p_xg);                                    // 5
    k_gemm<<<GEMMBLKS, 256>>>(p_xg, p_wt1, p_yraw);                            // 6
    k_bnfinish<<<1, 256>>>(gamma1, beta1);                                     // 7
    k_bnapply_nhwc<<<NPIX*CH/4/256, 256>>>(p_yraw);                            // 8

    // stage 2
    k_offconv<<<dim3(4, HH, BATCH), 288, OFF_SMEM>>>(p_y1n, woff2, boff2);     // 9
    k_gather<<<NPIX/32, 256>>>(p_y1n, p_xg);                                   // 10
    k_gemm<<<GEMMBLKS, 256>>>(p_xg, p_wt2, p_yraw);                            // 11
    k_bnfinish<<<1, 256>>>(gamma2, beta2);                                     // 12
    k_bnapply_nchw<<<NPIX/32, 256>>>(p_yraw, out);                             // 13
}

// round 5
// speedup vs baseline: 1.1179x; 1.0106x over previous
#include <cuda_runtime.h>

#define BATCH 2
#define CH 64
#define HH 224
#define WW 224
#define HW (HH*WW)           // 50176
#define NPIX (BATCH*HW)      // 100352
#define NOFF 18
#define KK 576               // 64*9
#define GEMMBLKS (NPIX/128)  // 784

typedef unsigned long long ull;

// ---------------- scratch (static device memory; no allocations) ----------------
__device__ float g_xh[NPIX*CH];      // NHWC input of current stage
__device__ float g_off[NPIX*NOFF];   // offsets NHWC
__device__ float g_xg[(size_t)NPIX*KK]; // gathered samples: xg[pix][i*64+c]
__device__ float g_yraw[NPIX*CH];    // pre-BN conv output NHWC
__device__ float g_y1n[NPIX*CH];     // stage-1 normalized output NHWC
__device__ float g_Wt1[KK*CH];       // Wt[(i*64+c)*64+o] = w_conv[o][c*9+i]
__device__ float g_Wt2[KK*CH];
__device__ float g_sp[GEMMBLKS*CH];  // partial sums (one row per gemm block)
__device__ float g_qp[GEMMBLKS*CH];  // partial sumsq
__device__ float g_ab[2*CH];         // per-channel scale a, shift b

#define FMA2(acc, w, x) asm("fma.rn.f32x2 %0, %1, %2, %0;" : "+l"(acc) : "l"(w), "l"(x))

// ---------------- NCHW -> NHWC transpose (+ fused conv-weight prep) ----------------
__global__ __launch_bounds__(256) void k_nchw2nhwc(const float* __restrict__ x,
                                                   const float* __restrict__ wconv1,
                                                   const float* __restrict__ wconv2,
                                                   float* __restrict__ wt1,
                                                   float* __restrict__ wt2) {
    __shared__ float tile[32][33];
    int b = blockIdx.z;
    int s0 = blockIdx.x * 32, c0 = blockIdx.y * 32;
    int tx = threadIdx.x, ty = threadIdx.y;
#pragma unroll
    for (int j = 0; j < 4; j++) {
        int c = c0 + ty + j*8;
        tile[ty + j*8][tx] = x[(b*CH + c)*HW + s0 + tx];
    }
    // fused weight prep: wt[(i*64+c)*64+o] = wconv[o][c*9+i]  (144 blocks x 256)
    if (blockIdx.y == 0 && blockIdx.z == 0 && blockIdx.x < 144) {
        int j = blockIdx.x * 256 + ty*32 + tx;
        int o = j & 63;
        int k = j >> 6;
        int i = k >> 6;
        int c = k & 63;
        wt1[j] = wconv1[o*KK + c*9 + i];
        wt2[j] = wconv2[o*KK + c*9 + i];
    }
    __syncthreads();
#pragma unroll
    for (int j = 0; j < 4; j++) {
        int s = s0 + ty + j*8;
        g_xh[(b*HW + s)*CH + c0 + tx] = tile[tx][ty + j*8];
    }
}

// ---------------- offset conv: 3x3, pad 1, 64->18 ch ----------------
// 128-px tile, 288 threads: warp = og-pair (og, og+9), lane = 4 pixels.
// patch [c][kx][132] (130 used), weights re-paired [og9][c][20] (18 used).
#define OFF_SMEM ((25344 + 11520) * 4)
__global__ __launch_bounds__(288, 1) void k_offconv(const float* __restrict__ in,
                                                    const float* __restrict__ woff,
                                                    const float* __restrict__ boff) {
    extern __shared__ float sm[];
    float* patch = sm;            // 64*396 = 25344 floats
    float* sW = sm + 25344;       // 9*64*20 = 11520 floats
    int t = threadIdx.x;
    int w0 = blockIdx.x * 128, h = blockIdx.y, b = blockIdx.z;

    for (int j = t; j < 11520; j += 288) {
        int og9 = j / 1280; int rem = j - og9*1280;
        int c = rem / 20; int k = rem - c*20;
        float v = 0.f;
        if (k < 18) {
            int tap = k >> 1, hh = k & 1;
            v = woff[(og9 + hh*9)*KK + c*9 + tap];
        }
        sW[j] = v;
    }
    for (int j = t; j < 3*130*64; j += 288) {
        int c = j & 63; int r = j >> 6; int p = r % 130; int kx = r / 130;
        int hr = h - 1 + kx; int wc = w0 - 1 + p;
        float v = 0.f;
        if ((unsigned)hr < (unsigned)HH && (unsigned)wc < (unsigned)WW)
            v = in[((b*HH + hr)*WW + wc)*CH + c];
        patch[c*396 + kx*132 + p] = v;
    }
    __syncthreads();

    int wid = t >> 5, lane = t & 31;
    int pp0 = lane * 4;
    ull acc[4] = {0ull, 0ull, 0ull, 0ull};
    const float* wbase = sW + wid*1280;
    for (int c = 0; c < CH; c++) {
        const float* pr = patch + c*396;
        const float* wp = wbase + c*20;
        ull w9[9];
#pragma unroll
        for (int tp = 0; tp < 9; tp++) w9[tp] = *(const ull*)(wp + tp*2);
#pragma unroll
        for (int kx = 0; kx < 3; kx++) {
            const float* row = pr + kx*132 + pp0;
            float4 v03 = *(const float4*)row;
            float2 v45 = *(const float2*)(row + 4);
            float v[6] = {v03.x, v03.y, v03.z, v03.w, v45.x, v45.y};
            ull d[6];
#pragma unroll
            for (int q = 0; q < 6; q++)
                asm("mov.b64 %0,{%1,%1};" : "=l"(d[q]) : "f"(v[q]));
#pragma unroll
            for (int ky = 0; ky < 3; ky++) {
                ull wv = w9[kx*3 + ky];
#pragma unroll
                for (int j = 0; j < 4; j++)
                    FMA2(acc[j], wv, d[j + ky]);
            }
        }
    }
    float b0 = boff[wid], b9 = boff[wid+9];
#pragma unroll
    for (int j = 0; j < 4; j++) {
        int w = w0 + pp0 + j;
        if (w < WW) {
            float lo, hi;
            asm("mov.b64 {%0,%1}, %2;" : "=f"(lo), "=f"(hi) : "l"(acc[j]));
            int base = ((b*HH + h)*WW + w)*NOFF;
            g_off[base + wid]     = lo + b0;
            g_off[base + wid + 9] = hi + b9;
        }
    }
}

// ---------------- gather: bilinear sample -> g_xg[pix][i*64+c] ----------------
__global__ __launch_bounds__(256) void k_gather(const float* __restrict__ in,
                                                float* __restrict__ xg) {
    __shared__ int4   gA[288];
    __shared__ float4 gW[288];
    __shared__ int    gO[288];
    int t = threadIdx.x;
    int pix0 = blockIdx.x * 32;
    int b = pix0 / HW; int hw = pix0 - b*HW;
    int h = hw / WW;  int w0 = hw - h*WW;

    for (int j = t; j < 288; j += 256) {
        int p = j / 9; int i = j - p*9;
        int pix = pix0 + p;
        float ox = g_off[pix*NOFF + i];
        float oy = g_off[pix*NOFF + 9 + i];
        float px = (float)(h + (i/3)) + ox;
        float py = (float)(w0 + p + (i%3)) + oy;
        float fx = floorf(px), fy = floorf(py);
        int x0 = (int)fx, y0 = (int)fy;
        int x1 = x0 + 1, y1 = y0 + 1;
        x0 = min(max(x0, 0), HH-1); x1 = min(max(x1, 0), HH-1);
        y0 = min(max(y0, 0), WW-1); y1 = min(max(y1, 0), WW-1);
        float pxc = fminf(fmaxf(px, 0.f), (float)(HH-1));
        float pyc = fminf(fmaxf(py, 0.f), (float)(WW-1));
        float wx0 = 1.f + (float)x0 - pxc;
        float wx1 = 1.f - (float)x1 + pxc;
        float wy0 = 1.f + (float)y0 - pyc;
        float wy1 = 1.f - (float)y1 + pyc;
        int base = b * HW;
        gA[j] = make_int4((base + x0*WW + y0)*CH, (base + x1*WW + y1)*CH,
                          (base + x0*WW + y1)*CH, (base + x1*WW + y0)*CH);
        gW[j] = make_float4(wx0*wy0, wx1*wy1, wx0*wy1, wx1*wy0);
        gO[j] = pix*KK + i*64;
    }
    __syncthreads();

    int c4 = (t & 15) * 4;
    int d0 = t >> 4;                 // group id 0..15
#pragma unroll 3
    for (int it = 0; it < 18; it++) {
        int desc = d0 + it*16;
        int4 a = gA[desc]; float4 g = gW[desc];
        float4 v0 = *(const float4*)(in + a.x + c4);
        float4 v1 = *(const float4*)(in + a.y + c4);
        float4 v2 = *(const float4*)(in + a.z + c4);
        float4 v3 = *(const float4*)(in + a.w + c4);
        float4 r;
        r.x = fmaf(g.w, v3.x, fmaf(g.z, v2.x, fmaf(g.y, v1.x, g.x*v0.x)));
        r.y = fmaf(g.w, v3.y, fmaf(g.z, v2.y, fmaf(g.y, v1.y, g.x*v0.y)));
        r.z = fmaf(g.w, v3.z, fmaf(g.z, v2.z, fmaf(g.y, v1.z, g.x*v0.z)));
        r.w = fmaf(g.w, v3.w, fmaf(g.z, v2.w, fmaf(g.y, v1.w, g.x*v0.w)));
        *(float4*)(xg + gO[desc] + c4) = r;
    }
}

// ---------------- GEMM + fused BN partial stats ----------------
__global__ __launch_bounds__(256, 3) void k_gemm(const float* __restrict__ xg,
                                                 const float* __restrict__ wt,
                                                 float* __restrict__ yout) {
    __shared__ float Xs[32*128];    // XOR-swizzled: [row k][phys col]
    __shared__ float Ws[32*64];
    int t = threadIdx.x;
    int pix0 = blockIdx.x * 128;
    int og = t & 15, pg = t >> 4;

    float4 xr[4]; float4 wr[2];

#pragma unroll
    for (int l = 0; l < 4; l++) {
        int idx = t + 256*l; int p = idx >> 3, kq = idx & 7;
        xr[l] = *(const float4*)(xg + (size_t)(pix0+p)*KK + kq*4);
    }
#pragma unroll
    for (int l = 0; l < 2; l++) {
        int idx = t + 256*l; int row = idx >> 4, q = idx & 15;
        wr[l] = *(const float4*)(wt + row*64 + q*4);
    }

    ull acc[4][4];
#pragma unroll
    for (int a = 0; a < 4; a++)
#pragma unroll
        for (int q = 0; q < 4; q++) acc[a][q] = 0ull;

    for (int kc = 0; kc < 18; kc++) {
        __syncthreads();
#pragma unroll
        for (int l = 0; l < 4; l++) {
            int idx = t + 256*l; int p = idx >> 3, kq = idx & 7;
#pragma unroll
            for (int j = 0; j < 4; j++) {
                int row = kq*4 + j;
                Xs[row*128 + (((p>>2) ^ kq) << 2) + (p & 3)] = (&xr[l].x)[j];
            }
        }
#pragma unroll
        for (int l = 0; l < 2; l++) {
            int idx = t + 256*l; int row = idx >> 4, q = idx & 15;
            *(float4*)(Ws + row*64 + q*4) = wr[l];
        }
        __syncthreads();

        if (kc < 17) {
            int k0 = (kc+1)*32;
#pragma unroll
            for (int l = 0; l < 4; l++) {
                int idx = t + 256*l; int p = idx >> 3, kq = idx & 7;
                xr[l] = *(const float4*)(xg + (size_t)(pix0+p)*KK + k0 + kq*4);
            }
#pragma unroll
            for (int l = 0; l < 2; l++) {
                int idx = t + 256*l; int row = idx >> 4, q = idx & 15;
                wr[l] = *(const float4*)(wt + (k0+row)*64 + q*4);
            }
        }

#pragma unroll
        for (int kk = 0; kk < 32; kk++) {
            float4 wv = *(const float4*)(Ws + kk*64 + og*4);
            int s = kk >> 2;
            const float* xrow = Xs + kk*128;
            int uA = (((pg*2)   ^ s) << 2);
            int uB = (((pg*2+1) ^ s) << 2);
            ull x0 = *(const ull*)(xrow + uA);
            ull x1 = *(const ull*)(xrow + uA + 2);
            ull x2 = *(const ull*)(xrow + uB);
            ull x3 = *(const ull*)(xrow + uB + 2);
#pragma unroll
            for (int a = 0; a < 4; a++) {
                float wa = (&wv.x)[a];
                ull w2;
                asm("mov.b64 %0, {%1, %1};" : "=l"(w2) : "f"(wa));
                FMA2(acc[a][0], w2, x0);
                FMA2(acc[a][1], w2, x1);
                FMA2(acc[a][2], w2, x2);
                FMA2(acc[a][3], w2, x3);
            }
        }
    }

    float s4[4] = {0,0,0,0}, q4[4] = {0,0,0,0};
#pragma unroll
    for (int q = 0; q < 4; q++) {
        float lo[4], hi[4];
#pragma unroll
        for (int a = 0; a < 4; a++) {
            asm("mov.b64 {%0, %1}, %2;" : "=f"(lo[a]), "=f"(hi[a]) : "l"(acc[a][q]));
            s4[a] += lo[a] + hi[a];
            q4[a] = fmaf(lo[a], lo[a], q4[a]);
            q4[a] = fmaf(hi[a], hi[a], q4[a]);
        }
        int p = pix0 + pg*8 + 2*q;
        *(float4*)(yout + (size_t)p*CH + og*4)     = make_float4(lo[0], lo[1], lo[2], lo[3]);
        *(float4*)(yout + (size_t)(p+1)*CH + og*4) = make_float4(hi[0], hi[1], hi[2], hi[3]);
    }
    __syncthreads();
    *(float4*)(Xs + pg*64 + og*4) = make_float4(s4[0], s4[1], s4[2], s4[3]);
    *(float4*)(Ws + pg*64 + og*4) = make_float4(q4[0], q4[1], q4[2], q4[3]);
    __syncthreads();
    if (t < 64) {
        float s = 0.f, qq = 0.f;
#pragma unroll
        for (int g = 0; g < 16; g++) { s += Xs[g*64 + t]; qq += Ws[g*64 + t]; }
        g_sp[blockIdx.x*64 + t] = s;
        g_qp[blockIdx.x*64 + t] = qq;
    }
}

// ---------------- BN finish: reduce 784 partials ----------------
__global__ __launch_bounds__(256) void k_bnfinish(const float* __restrict__ gamma,
                                                  const float* __restrict__ beta) {
    __shared__ float ss[256], sq[256];
    int t = threadIdx.x;
    int c = t & 63, sub = t >> 6;
    float s = 0.f, q = 0.f;
    for (int i = sub; i < GEMMBLKS; i += 4) {
        s += g_sp[i*64 + c];
        q += g_qp[i*64 + c];
    }
    ss[t] = s; sq[t] = q;
    __syncthreads();
    if (t < 64) {
        s = ss[t] + ss[t+64] + ss[t+128] + ss[t+192];
        q = sq[t] + sq[t+64] + sq[t+128] + sq[t+192];
        float inv = 1.f / (float)NPIX;
        float mean = s * inv;
        float var = fmaxf(q * inv - mean*mean, 0.f);
        float r = rsqrtf(var + 1e-5f);
        float a = gamma[t] * r;
        g_ab[t] = a;
        g_ab[64 + t] = beta[t] - mean * a;
    }
}

// ---------------- BN apply + relu, NHWC -> NHWC (stage-1 output) ----------------
__global__ __launch_bounds__(256) void k_bnapply_nhwc(const float* __restrict__ y) {
    int v = blockIdx.x * 256 + threadIdx.x;
    float4 t4 = ((const float4*)y)[v];
    int c = (v & 15) * 4;
    float4 r;
    r.x = fmaxf(fmaf(t4.x, g_ab[c+0], g_ab[64+c+0]), 0.f);
    r.y = fmaxf(fmaf(t4.y, g_ab[c+1], g_ab[64+c+1]), 0.f);
    r.z = fmaxf(fmaf(t4.z, g_ab[c+2], g_ab[64+c+2]), 0.f);
    r.w = fmaxf(fmaf(t4.w, g_ab[c+3], g_ab[64+c+3]), 0.f);
    ((float4*)g_y1n)[v] = r;
}

// ---------------- BN apply + relu + NHWC -> NCHW (final output) ----------------
__global__ __launch_bounds__(256) void k_bnapply_nchw(const float* __restrict__ y,
                                                      float* __restrict__ out) {
    __shared__ float tile[64*33];
    int t = threadIdx.x;
    int pix0 = blockIdx.x * 32;
    int b = pix0 / HW, hw0 = pix0 - b*HW;
    int c = t & 63, q = t >> 6;
    float a = g_ab[c], bb = g_ab[64 + c];
#pragma unroll
    for (int j = 0; j < 8; j++) {
        int p = q*8 + j;
        float v = y[(pix0 + p)*CH + c];
        tile[c*33 + p] = fmaxf(fmaf(v, a, bb), 0.f);
    }
    __syncthreads();
    int p2 = t & 31, cq = t >> 5;
#pragma unroll
    for (int j = 0; j < 8; j++) {
        int cc = cq*8 + j;
        out[(b*CH + cc)*HW + hw0 + p2] = tile[cc*33 + p2];
    }
}

// ---------------- launch ----------------
extern "C" void kernel_launch(void* const* d_in, const int* in_sizes, int n_in,
                              void* d_out, int out_size) {
    const float* x      = (const float*)d_in[0];
    const float* woff1  = (const float*)d_in[1];
    const float* boff1  = (const float*)d_in[2];
    const float* wconv1 = (const float*)d_in[3];
    const float* gamma1 = (const float*)d_in[4];
    const float* beta1  = (const float*)d_in[5];
    const float* woff2  = (const float*)d_in[6];
    const float* boff2  = (const float*)d_in[7];
    const float* wconv2 = (const float*)d_in[8];
    const float* gamma2 = (const float*)d_in[9];
    const float* beta2  = (const float*)d_in[10];
    float* out = (float*)d_out;

    float *p_xh, *p_y1n, *p_yraw, *p_xg, *p_wt1, *p_wt2;
    cudaGetSymbolAddress((void**)&p_xh,   g_xh);
    cudaGetSymbolAddress((void**)&p_y1n,  g_y1n);
    cudaGetSymbolAddress((void**)&p_yraw, g_yraw);
    cudaGetSymbolAddress((void**)&p_xg,   g_xg);
    cudaGetSymbolAddress((void**)&p_wt1,  g_Wt1);
    cudaGetSymbolAddress((void**)&p_wt2,  g_Wt2);

    cudaFuncSetAttribute(k_offconv, cudaFuncAttributeMaxDynamicSharedMemorySize, OFF_SMEM);

    // stage 1  (k_gemm is the 4th launch -> lands in the ncu capture slot)
    k_nchw2nhwc<<<dim3(HW/32, 2, BATCH), dim3(32, 8)>>>(x, wconv1, wconv2, p_wt1, p_wt2); // 1
    k_offconv<<<dim3(2, HH, BATCH), 288, OFF_SMEM>>>(p_xh, woff1, boff1);      // 2
    k_gather<<<NPIX/32, 256>>>(p_xh, p_xg);                                    // 3
    k_gemm<<<GEMMBLKS, 256>>>(p_xg, p_wt1, p_yraw);                            // 4
    k_bnfinish<<<1, 256>>>(gamma1, beta1);                                     // 5
    k_bnapply_nhwc<<<NPIX*CH/4/256, 256>>>(p_yraw);                            // 6

    // stage 2
    k_offconv<<<dim3(2, HH, BATCH), 288, OFF_SMEM>>>(p_y1n, woff2, boff2);     // 7
    k_gather<<<NPIX/32, 256>>>(p_y1n, p_xg);                                   // 8
    k_gemm<<<GEMMBLKS, 256>>>(p_xg, p_wt2, p_yraw);                            // 9
    k_bnfinish<<<1, 256>>>(gamma2, beta2);                                     // 10
    k_bnapply_nchw<<<NPIX/32, 256>>>(p_yraw, out);                             // 11
}

// round 8
// speedup vs baseline: 1.4278x; 1.2772x over previous
#include <cstdint>
#include <cstring>
#include <cuda_runtime.h>
#include <cuda_bf16.h>

#define BATCH 2
#define CH 64
#define HH 224
#define WW 224
#define HW (HH*WW)           // 50176
#define NPIX (BATCH*HW)      // 100352
#define NOFF 18
#define KK 576               // 64*9
#define GEMMBLKS (NPIX/128)  // 784

typedef unsigned long long ull;

// ---------------- scratch (static device memory; no allocations) ----------------
__device__ float g_xh[NPIX*CH];              // NHWC input of current stage
__device__ float g_off[NPIX*NOFF];           // offsets NHWC
__device__ __nv_bfloat16 g_xgh[(size_t)NPIX*KK];  // gathered samples hi
__device__ __nv_bfloat16 g_xgl[(size_t)NPIX*KK];  // gathered samples lo
__device__ float g_yraw[NPIX*CH];            // pre-BN conv output NHWC
__device__ float g_y1n[NPIX*CH];             // stage-1 normalized output NHWC
__device__ __nv_bfloat16 g_wh1[9*CH*CH];     // W hi: [kc][och][c]
__device__ __nv_bfloat16 g_wl1[9*CH*CH];
__device__ __nv_bfloat16 g_wh2[9*CH*CH];
__device__ __nv_bfloat16 g_wl2[9*CH*CH];
__device__ float g_sp[GEMMBLKS*CH];          // partial sums
__device__ float g_qp[GEMMBLKS*CH];          // partial sumsq
__device__ float g_ab[2*CH];                 // per-channel scale a, shift b

#define FMA2(acc, w, x) asm("fma.rn.f32x2 %0, %1, %2, %0;" : "+l"(acc) : "l"(w), "l"(x))

__device__ __forceinline__ uint32_t smem_u32(const void* p) {
    uint32_t a;
    asm("{ .reg .u64 t; cvta.to.shared.u64 t, %1; cvt.u32.u64 %0, t; }" : "=r"(a) : "l"(p));
    return a;
}
__device__ __forceinline__ void sts128(uint32_t a, uint4 v) {
    asm volatile("st.shared.v4.b32 [%0], {%1,%2,%3,%4};"
                 :: "r"(a), "r"(v.x), "r"(v.y), "r"(v.z), "r"(v.w) : "memory");
}
__device__ __forceinline__ void ldsm4(uint32_t* r, uint32_t addr) {
    asm volatile("ldmatrix.sync.aligned.m8n8.x4.shared.b16 {%0,%1,%2,%3}, [%4];"
                 : "=r"(r[0]), "=r"(r[1]), "=r"(r[2]), "=r"(r[3]) : "r"(addr));
}
__device__ __forceinline__ void mma16816(float* d, const uint32_t* a, uint32_t b0, uint32_t b1) {
    asm volatile(
        "mma.sync.aligned.m16n8k16.row.col.f32.bf16.bf16.f32 "
        "{%0,%1,%2,%3}, {%4,%5,%6,%7}, {%8,%9}, {%0,%1,%2,%3};"
        : "+f"(d[0]), "+f"(d[1]), "+f"(d[2]), "+f"(d[3])
        : "r"(a[0]), "r"(a[1]), "r"(a[2]), "r"(a[3]), "r"(b0), "r"(b1));
}

// ---------------- NCHW -> NHWC transpose (+ fused bf16 W split prep) ----------------
__global__ __launch_bounds__(256) void k_nchw2nhwc(const float* __restrict__ x,
                                                   const float* __restrict__ wconv1,
                                                   const float* __restrict__ wconv2) {
    __shared__ float tile[32][33];
    int b = blockIdx.z;
    int s0 = blockIdx.x * 32, c0 = blockIdx.y * 32;
    int tx = threadIdx.x, ty = threadIdx.y;
#pragma unroll
    for (int j = 0; j < 4; j++) {
        int c = c0 + ty + j*8;
        tile[ty + j*8][tx] = x[(b*CH + c)*HW + s0 + tx];
    }
    // fused weight prep: Wh[kc*4096 + och*64 + cl] = bf16(wconv[och][cl*9+kc]); lo = residual
    if (blockIdx.y == 0 && blockIdx.z == 0 && blockIdx.x < 144) {
        int j = blockIdx.x * 256 + ty*32 + tx;
        int cl = j & 63, och = (j >> 6) & 63, kc = j >> 12;
        float w1 = wconv1[och*KK + cl*9 + kc];
        __nv_bfloat16 h1 = __float2bfloat16(w1);
        g_wh1[j] = h1;
        g_wl1[j] = __float2bfloat16(w1 - __bfloat162float(h1));
        float w2 = wconv2[och*KK + cl*9 + kc];
        __nv_bfloat16 h2 = __float2bfloat16(w2);
        g_wh2[j] = h2;
        g_wl2[j] = __float2bfloat16(w2 - __bfloat162float(h2));
    }
    __syncthreads();
#pragma unroll
    for (int j = 0; j < 4; j++) {
        int s = s0 + ty + j*8;
        g_xh[(b*HW + s)*CH + c0 + tx] = tile[tx][ty + j*8];
    }
}

// ---------------- offset conv: 3x3, pad 1, 64->18 ch ----------------
#define OFF_SMEM ((25344 + 11520) * 4)
__global__ __launch_bounds__(288, 1) void k_offconv(const float* __restrict__ in,
                                                    const float* __restrict__ woff,
                                                    const float* __restrict__ boff) {
    extern __shared__ float sm[];
    float* patch = sm;            // 64*396 = 25344 floats
    float* sW = sm + 25344;       // 9*64*20 = 11520 floats
    int t = threadIdx.x;
    int w0 = blockIdx.x * 128, h = blockIdx.y, b = blockIdx.z;

    for (int j = t; j < 11520; j += 288) {
        int og9 = j / 1280; int rem = j - og9*1280;
        int c = rem / 20; int k = rem - c*20;
        float v = 0.f;
        if (k < 18) {
            int tap = k >> 1, hh = k & 1;
            v = woff[(og9 + hh*9)*KK + c*9 + tap];
        }
        sW[j] = v;
    }
    for (int j = t; j < 3*130*64; j += 288) {
        int c = j & 63; int r = j >> 6; int p = r % 130; int kx = r / 130;
        int hr = h - 1 + kx; int wc = w0 - 1 + p;
        float v = 0.f;
        if ((unsigned)hr < (unsigned)HH && (unsigned)wc < (unsigned)WW)
            v = in[((b*HH + hr)*WW + wc)*CH + c];
        patch[c*396 + kx*132 + p] = v;
    }
    __syncthreads();

    int wid = t >> 5, lane = t & 31;
    int pp0 = lane * 4;
    ull acc[4] = {0ull, 0ull, 0ull, 0ull};
    const float* wbase = sW + wid*1280;
    for (int c = 0; c < CH; c++) {
        const float* pr = patch + c*396;
        const float* wp = wbase + c*20;
        ull w9[9];
#pragma unroll
        for (int tp = 0; tp < 9; tp++) w9[tp] = *(const ull*)(wp + tp*2);
#pragma unroll
        for (int kx = 0; kx < 3; kx++) {
            const float* row = pr + kx*132 + pp0;
            float4 v03 = *(const float4*)row;
            float2 v45 = *(const float2*)(row + 4);
            float v[6] = {v03.x, v03.y, v03.z, v03.w, v45.x, v45.y};
            ull d[6];
#pragma unroll
            for (int q = 0; q < 6; q++)
                asm("mov.b64 %0,{%1,%1};" : "=l"(d[q]) : "f"(v[q]));
#pragma unroll
            for (int ky = 0; ky < 3; ky++) {
                ull wv = w9[kx*3 + ky];
#pragma unroll
                for (int j = 0; j < 4; j++)
                    FMA2(acc[j], wv, d[j + ky]);
            }
        }
    }
    float b0 = boff[wid], b9 = boff[wid+9];
#pragma unroll
    for (int j = 0; j < 4; j++) {
        int w = w0 + pp0 + j;
        if (w < WW) {
            float lo, hi;
            asm("mov.b64 {%0,%1}, %2;" : "=f"(lo), "=f"(hi) : "l"(acc[j]));
            int base = ((b*HH + h)*WW + w)*NOFF;
            g_off[base + wid]     = lo + b0;
            g_off[base + wid + 9] = hi + b9;
        }
    }
}

// ---------------- gather: bilinear sample -> bf16 hi/lo ----------------
__global__ __launch_bounds__(256) void k_gather(const float* __restrict__ in,
                                                __nv_bfloat16* __restrict__ xgh,
                                                __nv_bfloat16* __restrict__ xgl) {
    __shared__ int4   gA[288];
    __shared__ float4 gW[288];
    __shared__ int    gO[288];
    int t = threadIdx.x;
    int pix0 = blockIdx.x * 32;
    int b = pix0 / HW; int hw = pix0 - b*HW;
    int h = hw / WW;  int w0 = hw - h*WW;

    for (int j = t; j < 288; j += 256) {
        int p = j / 9; int i = j - p*9;
        int pix = pix0 + p;
        float ox = g_off[pix*NOFF + i];
        float oy = g_off[pix*NOFF + 9 + i];
        float px = (float)(h + (i/3)) + ox;
        float py = (float)(w0 + p + (i%3)) + oy;
        float fx = floorf(px), fy = floorf(py);
        int x0 = (int)fx, y0 = (int)fy;
        int x1 = x0 + 1, y1 = y0 + 1;
        x0 = min(max(x0, 0), HH-1); x1 = min(max(x1, 0), HH-1);
        y0 = min(max(y0, 0), WW-1); y1 = min(max(y1, 0), WW-1);
        float pxc = fminf(fmaxf(px, 0.f), (float)(HH-1));
        float pyc = fminf(fmaxf(py, 0.f), (float)(WW-1));
        float wx0 = 1.f + (float)x0 - pxc;
        float wx1 = 1.f - (float)x1 + pxc;
        float wy0 = 1.f + (float)y0 - pyc;
        float wy1 = 1.f - (float)y1 + pyc;
        int base = b * HW;
        gA[j] = make_int4((base + x0*WW + y0)*CH, (base + x1*WW + y1)*CH,
                          (base + x0*WW + y1)*CH, (base + x1*WW + y0)*CH);
        gW[j] = make_float4(wx0*wy0, wx1*wy1, wx0*wy1, wx1*wy0);
        gO[j] = pix*KK + i*64;
    }
    __syncthreads();

    int c4 = (t & 15) * 4;
    int d0 = t >> 4;
#pragma unroll 3
    for (int it = 0; it < 18; it++) {
        int desc = d0 + it*16;
        int4 a = gA[desc]; float4 g = gW[desc];
        float4 v0 = *(const float4*)(in + a.x + c4);
        float4 v1 = *(const float4*)(in + a.y + c4);
        float4 v2 = *(const float4*)(in + a.z + c4);
        float4 v3 = *(const float4*)(in + a.w + c4);
        float4 r;
        r.x = fmaf(g.w, v3.x, fmaf(g.z, v2.x, fmaf(g.y, v1.x, g.x*v0.x)));
        r.y = fmaf(g.w, v3.y, fmaf(g.z, v2.y, fmaf(g.y, v1.y, g.x*v0.y)));
        r.z = fmaf(g.w, v3.z, fmaf(g.z, v2.z, fmaf(g.y, v1.z, g.x*v0.z)));
        r.w = fmaf(g.w, v3.w, fmaf(g.z, v2.w, fmaf(g.y, v1.w, g.x*v0.w)));
        __nv_bfloat162 h01 = __floats2bfloat162_rn(r.x, r.y);
        __nv_bfloat162 h23 = __floats2bfloat162_rn(r.z, r.w);
        float2 f01 = __bfloat1622float2(h01);
        float2 f23 = __bfloat1622float2(h23);
        __nv_bfloat162 l01 = __floats2bfloat162_rn(r.x - f01.x, r.y - f01.y);
        __nv_bfloat162 l23 = __floats2bfloat162_rn(r.z - f23.x, r.w - f23.y);
        unsigned int uh01, uh23, ul01, ul23;
        memcpy(&uh01, &h01, 4); memcpy(&uh23, &h23, 4);
        memcpy(&ul01, &l01, 4); memcpy(&ul23, &l23, 4);
        size_t off = (size_t)gO[desc] + c4;
        *(uint2*)(xgh + off) = make_uint2(uh01, uh23);
        *(uint2*)(xgl + off) = make_uint2(ul01, ul23);
    }
}

// ---------------- mma.sync bf16 GEMM: 128px x 64och, K=576, hi/lo split ----------------
// smem: Ah[128x64 bf16] Al[...] Bh[64x64] Bl[64x64]; per-row XOR-16B swizzle.
#define SM_AH   0
#define SM_AL   16384
#define SM_BH   32768
#define SM_BL   40960
#define SM_TOTAL 49152

__global__ __launch_bounds__(256, 2)
void k_gemmtc(const __nv_bfloat16* __restrict__ xh,
              const __nv_bfloat16* __restrict__ xl,
              const __nv_bfloat16* __restrict__ wh,
              const __nv_bfloat16* __restrict__ wl,
              float* __restrict__ yout) {
    extern __shared__ char smem[];
    uint32_t sb = smem_u32(smem);
    int t = threadIdx.x;
    int w = t >> 5, lane = t & 31;
    int pix0 = blockIdx.x * 128;

    // global load mapping (same as round-5): A px = t>>1, half = t&1; B och = t>>2, q = t&3
    int apx = t >> 1, ahalf = t & 1;
    int boch = t >> 2, bq = t & 3;
    const uint4* gah = (const uint4*)(xh + (size_t)(pix0 + apx)*KK) + ahalf*4;
    const uint4* gal = (const uint4*)(xl + (size_t)(pix0 + apx)*KK) + ahalf*4;
    const uint4* gbh = (const uint4*)wh + boch*8 + bq*2;
    const uint4* gbl = (const uint4*)wl + boch*8 + bq*2;
    int asw = apx & 7, bsw = boch & 7;

    // ldmatrix address precompute: m = lane>>3 (matrix), r = lane&7 (row in matrix)
    int m = lane >> 3, r = lane & 7;
    int arow = 16*w + (m & 1)*8 + r;        // A row for matrices m0..m3
    uint32_t aRowOff = (uint32_t)arow * 128;
    int ac0 = m >> 1;                        // A col16 offset (k-half)
    int bochp = (m >> 1)*8 + r;              // B row within 16-och pair-tile
    int bc0 = m & 1;                         // B col16 offset (k-half)

    float acc[8][4];
#pragma unroll
    for (int n = 0; n < 8; n++)
#pragma unroll
        for (int j = 0; j < 4; j++) acc[n][j] = 0.f;

    uint4 ra[4], rl[4], rbh[2], rbl[2];
#define LOADCH(kc) do { \
        ra[0]=gah[(kc)*8+0]; ra[1]=gah[(kc)*8+1]; ra[2]=gah[(kc)*8+2]; ra[3]=gah[(kc)*8+3]; \
        rl[0]=gal[(kc)*8+0]; rl[1]=gal[(kc)*8+1]; rl[2]=gal[(kc)*8+2]; rl[3]=gal[(kc)*8+3]; \
        rbh[0]=gbh[(kc)*512+0]; rbh[1]=gbh[(kc)*512+1]; \
        rbl[0]=gbl[(kc)*512+0]; rbl[1]=gbl[(kc)*512+1]; \
    } while (0)

    LOADCH(0);
    for (int kc = 0; kc < 9; kc++) {
        __syncthreads();
#pragma unroll
        for (int q = 0; q < 4; q++) {
            uint32_t o = (uint32_t)apx*128 + (uint32_t)(((ahalf*4 + q) ^ asw) << 4);
            sts128(sb + SM_AH + o, ra[q]);
            sts128(sb + SM_AL + o, rl[q]);
        }
#pragma unroll
        for (int q = 0; q < 2; q++) {
            uint32_t o = (uint32_t)boch*128 + (uint32_t)(((bq*2 + q) ^ bsw) << 4);
            sts128(sb + SM_BH + o, rbh[q]);
            sts128(sb + SM_BL + o, rbl[q]);
        }
        __syncthreads();
        if (kc < 8) LOADCH(kc + 1);

#pragma unroll
        for (int kk = 0; kk < 4; kk++) {
            uint32_t ah[4], al[4];
            uint32_t ao = aRowOff + (uint32_t)(((kk*2 + ac0) ^ r) << 4);
            ldsm4(ah, sb + SM_AH + ao);
            ldsm4(al, sb + SM_AL + ao);
            uint32_t bco = (uint32_t)(((kk*2 + bc0) ^ r) << 4);
#pragma unroll
            for (int nt = 0; nt < 4; nt++) {
                uint32_t bh[4], bl[4];
                uint32_t bo = (uint32_t)(16*nt + bochp)*128 + bco;
                ldsm4(bh, sb + SM_BH + bo);
                ldsm4(bl, sb + SM_BL + bo);
                mma16816(acc[2*nt],   ah, bh[0], bh[1]);
                mma16816(acc[2*nt+1], ah, bh[2], bh[3]);
                mma16816(acc[2*nt],   ah, bl[0], bl[1]);
                mma16816(acc[2*nt+1], ah, bl[2], bl[3]);
                mma16816(acc[2*nt],   al, bh[0], bh[1]);
                mma16816(acc[2*nt+1], al, bh[2], bh[3]);
            }
        }
    }
#undef LOADCH

    // epilogue: stage D (128x64 fp32) in smem, fused BN partials + coalesced store
    __syncthreads();
    float* stg = (float*)smem;             // 32 KB, overlays A tiles
    int g = lane >> 2, tid4 = lane & 3;
#pragma unroll
    for (int n = 0; n < 8; n++) {
        int row0 = 16*w + g;
        int col = n*8 + tid4*2;
        *(float2*)(stg + row0*64 + col)     = make_float2(acc[n][0], acc[n][1]);
        *(float2*)(stg + (row0+8)*64 + col) = make_float2(acc[n][2], acc[n][3]);
    }
    __syncthreads();

    int och = t & 63, grp = t >> 6;
    float s = 0.f, q = 0.f;
#pragma unroll 4
    for (int j = 0; j < 32; j++) {
        float v = stg[(grp*32 + j)*64 + och];
        s += v;
        q = fmaf(v, v, q);
    }
    float* rs = (float*)(smem + SM_BH);
    float* rq = rs + 256;
    rs[t] = s; rq[t] = q;

    float4* stg4 = (float4*)stg;
    float4* y4 = (float4*)(yout + (size_t)pix0*CH);
#pragma unroll
    for (int j = 0; j < 8; j++) y4[j*256 + t] = stg4[j*256 + t];

    __syncthreads();
    if (t < 64) {
        s = rs[t] + rs[t+64] + rs[t+128] + rs[t+192];
        q = rq[t] + rq[t+64] + rq[t+128] + rq[t+192];
        g_sp[blockIdx.x*64 + t] = s;
        g_qp[blockIdx.x*64 + t] = q;
    }
}

// ---------------- BN finish: reduce 784 partials ----------------
__global__ __launch_bounds__(256) void k_bnfinish(const float* __restrict__ gamma,
                                                  const float* __restrict__ beta) {
    __shared__ float ss[256], sq[256];
    int t = threadIdx.x;
    int c = t & 63, sub = t >> 6;
    float s = 0.f, q = 0.f;
    for (int i = sub; i < GEMMBLKS; i += 4) {
        s += g_sp[i*64 + c];
        q += g_qp[i*64 + c];
    }
    ss[t] = s; sq[t] = q;
    __syncthreads();
    if (t < 64) {
        s = ss[t] + ss[t+64] + ss[t+128] + ss[t+192];
        q = sq[t] + sq[t+64] + sq[t+128] + sq[t+192];
        float inv = 1.f / (float)NPIX;
        float mean = s * inv;
        float var = fmaxf(q * inv - mean*mean, 0.f);
        float r = rsqrtf(var + 1e-5f);
        float a = gamma[t] * r;
        g_ab[t] = a;
        g_ab[64 + t] = beta[t] - mean * a;
    }
}

// ---------------- BN apply + relu, NHWC -> NHWC (stage-1 output) ----------------
__global__ __launch_bounds__(256) void k_bnapply_nhwc(const float* __restrict__ y) {
    int v = blockIdx.x * 256 + threadIdx.x;
    float4 t4 = ((const float4*)y)[v];
    int c = (v & 15) * 4;
    float4 r;
    r.x = fmaxf(fmaf(t4.x, g_ab[c+0], g_ab[64+c+0]), 0.f);
    r.y = fmaxf(fmaf(t4.y, g_ab[c+1], g_ab[64+c+1]), 0.f);
    r.z = fmaxf(fmaf(t4.z, g_ab[c+2], g_ab[64+c+2]), 0.f);
    r.w = fmaxf(fmaf(t4.w, g_ab[c+3], g_ab[64+c+3]), 0.f);
    ((float4*)g_y1n)[v] = r;
}

// ---------------- BN apply + relu + NHWC -> NCHW (final output) ----------------
__global__ __launch_bounds__(256) void k_bnapply_nchw(const float* __restrict__ y,
                                                      float* __restrict__ out) {
    __shared__ float tile[64*33];
    int t = threadIdx.x;
    int pix0 = blockIdx.x * 32;
    int b = pix0 / HW, hw0 = pix0 - b*HW;
    int c = t & 63, q = t >> 6;
    float a = g_ab[c], bb = g_ab[64 + c];
#pragma unroll
    for (int j = 0; j < 8; j++) {
        int p = q*8 + j;
        float v = y[(pix0 + p)*CH + c];
        tile[c*33 + p] = fmaxf(fmaf(v, a, bb), 0.f);
    }
    __syncthreads();
    int p2 = t & 31, cq = t >> 5;
#pragma unroll
    for (int j = 0; j < 8; j++) {
        int cc = cq*8 + j;
        out[(b*CH + cc)*HW + hw0 + p2] = tile[cc*33 + p2];
    }
}

// ---------------- launch ----------------
extern "C" void kernel_launch(void* const* d_in, const int* in_sizes, int n_in,
                              void* d_out, int out_size) {
    const float* x      = (const float*)d_in[0];
    const float* woff1  = (const float*)d_in[1];
    const float* boff1  = (const float*)d_in[2];
    const float* wconv1 = (const float*)d_in[3];
    const float* gamma1 = (const float*)d_in[4];
    const float* beta1  = (const float*)d_in[5];
    const float* woff2  = (const float*)d_in[6];
    const float* boff2  = (const float*)d_in[7];
    const float* wconv2 = (const float*)d_in[8];
    const float* gamma2 = (const float*)d_in[9];
    const float* beta2  = (const float*)d_in[10];
    float* out = (float*)d_out;

    float *p_xh, *p_y1n, *p_yraw;
    __nv_bfloat16 *p_xgh, *p_xgl, *p_wh1, *p_wl1, *p_wh2, *p_wl2;
    cudaGetSymbolAddress((void**)&p_xh,   g_xh);
    cudaGetSymbolAddress((void**)&p_y1n,  g_y1n);
    cudaGetSymbolAddress((void**)&p_yraw, g_yraw);
    cudaGetSymbolAddress((void**)&p_xgh,  g_xgh);
    cudaGetSymbolAddress((void**)&p_xgl,  g_xgl);
    cudaGetSymbolAddress((void**)&p_wh1,  g_wh1);
    cudaGetSymbolAddress((void**)&p_wl1,  g_wl1);
    cudaGetSymbolAddress((void**)&p_wh2,  g_wh2);
    cudaGetSymbolAddress((void**)&p_wl2,  g_wl2);

    cudaFuncSetAttribute(k_offconv, cudaFuncAttributeMaxDynamicSharedMemorySize, OFF_SMEM);
    cudaFuncSetAttribute(k_gemmtc,  cudaFuncAttributeMaxDynamicSharedMemorySize, SM_TOTAL);

    // stage 1  (k_gemmtc is launch 4 -> ncu capture slot)
    k_nchw2nhwc<<<dim3(HW/32, 2, BATCH), dim3(32, 8)>>>(x, wconv1, wconv2);    // 1
    k_offconv<<<dim3(2, HH, BATCH), 288, OFF_SMEM>>>(p_xh, woff1, boff1);      // 2
    k_gather<<<NPIX/32, 256>>>(p_xh, p_xgh, p_xgl);                            // 3
    k_gemmtc<<<GEMMBLKS, 256, SM_TOTAL>>>(p_xgh, p_xgl, p_wh1, p_wl1, p_yraw); // 4
    k_bnfinish<<<1, 256>>>(gamma1, beta1);                                     // 5
    k_bnapply_nhwc<<<NPIX*CH/4/256, 256>>>(p_yraw);                            // 6

    // stage 2
    k_offconv<<<dim3(2, HH, BATCH), 288, OFF_SMEM>>>(p_y1n, woff2, boff2);     // 7
    k_gather<<<NPIX/32, 256>>>(p_y1n, p_xgh, p_xgl);                           // 8
    k_gemmtc<<<GEMMBLKS, 256, SM_TOTAL>>>(p_xgh, p_xgl, p_wh2, p_wl2, p_yraw); // 9
    k_bnfinish<<<1, 256>>>(gamma2, beta2);                                     // 10
    k_bnapply_nchw<<<NPIX/32, 256>>>(p_yraw, out);                             // 11
}

// round 9
// speedup vs baseline: 1.4451x; 1.0121x over previous
#include <cstdint>
#include <cstring>
#include <cuda_runtime.h>
#include <cuda_bf16.h>

#define BATCH 2
#define CH 64
#define HH 224
#define WW 224
#define HW (HH*WW)           // 50176
#define NPIX (BATCH*HW)      // 100352
#define NOFF 18
#define KK 576               // 64*9
#define GEMMBLKS (NPIX/128)  // 784

typedef unsigned long long ull;

// ---------------- scratch (static device memory; no allocations) ----------------
__device__ float g_xh[NPIX*CH];              // NHWC input of current stage
__device__ float g_off[NPIX*NOFF];           // offsets NHWC
__device__ __nv_bfloat16 g_xgh[(size_t)NPIX*KK];  // gathered samples hi
__device__ __nv_bfloat16 g_xgl[(size_t)NPIX*KK];  // gathered samples lo
__device__ float g_yraw[NPIX*CH];            // pre-BN conv output NHWC
__device__ float g_y1n[NPIX*CH];             // stage-1 normalized output NHWC
__device__ __nv_bfloat16 g_wh1[9*CH*CH];     // W hi: [kc][och][c]
__device__ __nv_bfloat16 g_wl1[9*CH*CH];
__device__ __nv_bfloat16 g_wh2[9*CH*CH];
__device__ __nv_bfloat16 g_wl2[9*CH*CH];
__device__ float g_sp[GEMMBLKS*CH];          // partial sums
__device__ float g_qp[GEMMBLKS*CH];          // partial sumsq
__device__ float g_ab[2*CH];                 // per-channel scale a, shift b

#define FMA2(acc, w, x) asm("fma.rn.f32x2 %0, %1, %2, %0;" : "+l"(acc) : "l"(w), "l"(x))

__device__ __forceinline__ uint32_t smem_u32(const void* p) {
    uint32_t a;
    asm("{ .reg .u64 t; cvta.to.shared.u64 t, %1; cvt.u32.u64 %0, t; }" : "=r"(a) : "l"(p));
    return a;
}
__device__ __forceinline__ void sts128(uint32_t a, uint4 v) {
    asm volatile("st.shared.v4.b32 [%0], {%1,%2,%3,%4};"
                 :: "r"(a), "r"(v.x), "r"(v.y), "r"(v.z), "r"(v.w) : "memory");
}
__device__ __forceinline__ void ldsm4(uint32_t* r, uint32_t addr) {
    asm volatile("ldmatrix.sync.aligned.m8n8.x4.shared.b16 {%0,%1,%2,%3}, [%4];"
                 : "=r"(r[0]), "=r"(r[1]), "=r"(r[2]), "=r"(r[3]) : "r"(addr));
}
__device__ __forceinline__ void mma16816(float* d, const uint32_t* a, uint32_t b0, uint32_t b1) {
    asm volatile(
        "mma.sync.aligned.m16n8k16.row.col.f32.bf16.bf16.f32 "
        "{%0,%1,%2,%3}, {%4,%5,%6,%7}, {%8,%9}, {%0,%1,%2,%3};"
        : "+f"(d[0]), "+f"(d[1]), "+f"(d[2]), "+f"(d[3])
        : "r"(a[0]), "r"(a[1]), "r"(a[2]), "r"(a[3]), "r"(b0), "r"(b1));
}

// ---------------- NCHW -> NHWC transpose ----------------
__global__ __launch_bounds__(256) void k_nchw2nhwc(const float* __restrict__ x) {
    __shared__ float tile[32][33];
    int b = blockIdx.z;
    int s0 = blockIdx.x * 32, c0 = blockIdx.y * 32;
    int tx = threadIdx.x, ty = threadIdx.y;
#pragma unroll
    for (int j = 0; j < 4; j++) {
        int c = c0 + ty + j*8;
        tile[ty + j*8][tx] = x[(b*CH + c)*HW + s0 + tx];
    }
    __syncthreads();
#pragma unroll
    for (int j = 0; j < 4; j++) {
        int s = s0 + ty + j*8;
        g_xh[(b*HW + s)*CH + c0 + tx] = tile[tx][ty + j*8];
    }
}

// ---------------- bf16 W split prep: Wh[kc][och][cl] + residual ----------------
__global__ void k_prepw(const float* __restrict__ wconv,
                        __nv_bfloat16* __restrict__ wh,
                        __nv_bfloat16* __restrict__ wl) {
    int j = blockIdx.x * 256 + threadIdx.x;   // 144 blocks x 256 = 36864
    int cl = j & 63, och = (j >> 6) & 63, kc = j >> 12;
    float wv = wconv[och*KK + cl*9 + kc];
    __nv_bfloat16 h = __float2bfloat16(wv);
    wh[j] = h;
    wl[j] = __float2bfloat16(wv - __bfloat162float(h));
}

// ---------------- offset conv: 3x3, pad 1, 64->18 ch ----------------
#define OFF_SMEM ((25344 + 11520) * 4)
__global__ __launch_bounds__(288, 1) void k_offconv(const float* __restrict__ in,
                                                    const float* __restrict__ woff,
                                                    const float* __restrict__ boff) {
    extern __shared__ float sm[];
    float* patch = sm;            // 64*396 = 25344 floats
    float* sW = sm + 25344;       // 9*64*20 = 11520 floats
    int t = threadIdx.x;
    int w0 = blockIdx.x * 128, h = blockIdx.y, b = blockIdx.z;

    for (int j = t; j < 11520; j += 288) {
        int og9 = j / 1280; int rem = j - og9*1280;
        int c = rem / 20; int k = rem - c*20;
        float v = 0.f;
        if (k < 18) {
            int tap = k >> 1, hh = k & 1;
            v = woff[(og9 + hh*9)*KK + c*9 + tap];
        }
        sW[j] = v;
    }
    for (int j = t; j < 3*130*64; j += 288) {
        int c = j & 63; int r = j >> 6; int p = r % 130; int kx = r / 130;
        int hr = h - 1 + kx; int wc = w0 - 1 + p;
        float v = 0.f;
        if ((unsigned)hr < (unsigned)HH && (unsigned)wc < (unsigned)WW)
            v = in[((b*HH + hr)*WW + wc)*CH + c];
        patch[c*396 + kx*132 + p] = v;
    }
    __syncthreads();

    int wid = t >> 5, lane = t & 31;
    int pp0 = lane * 4;
    ull acc[4] = {0ull, 0ull, 0ull, 0ull};
    const float* wbase = sW + wid*1280;
    for (int c = 0; c < CH; c++) {
        const float* pr = patch + c*396;
        const float* wp = wbase + c*20;
        ull w9[9];
#pragma unroll
        for (int tp = 0; tp < 9; tp++) w9[tp] = *(const ull*)(wp + tp*2);
#pragma unroll
        for (int kx = 0; kx < 3; kx++) {
            const float* row = pr + kx*132 + pp0;
            float4 v03 = *(const float4*)row;
            float2 v45 = *(const float2*)(row + 4);
            float v[6] = {v03.x, v03.y, v03.z, v03.w, v45.x, v45.y};
            ull d[6];
#pragma unroll
            for (int q = 0; q < 6; q++)
                asm("mov.b64 %0,{%1,%1};" : "=l"(d[q]) : "f"(v[q]));
#pragma unroll
            for (int ky = 0; ky < 3; ky++) {
                ull wv = w9[kx*3 + ky];
#pragma unroll
                for (int j = 0; j < 4; j++)
                    FMA2(acc[j], wv, d[j + ky]);
            }
        }
    }
    float b0 = boff[wid], b9 = boff[wid+9];
#pragma unroll
    for (int j = 0; j < 4; j++) {
        int w = w0 + pp0 + j;
        if (w < WW) {
            float lo, hi;
            asm("mov.b64 {%0,%1}, %2;" : "=f"(lo), "=f"(hi) : "l"(acc[j]));
            int base = ((b*HH + h)*WW + w)*NOFF;
            g_off[base + wid]     = lo + b0;
            g_off[base + wid + 9] = hi + b9;
        }
    }
}

// ---------------- gather: bilinear sample -> bf16 hi/lo ----------------
__global__ __launch_bounds__(256) void k_gather(const float* __restrict__ in,
                                                __nv_bfloat16* __restrict__ xgh,
                                                __nv_bfloat16* __restrict__ xgl) {
    __shared__ int4   gA[288];
    __shared__ float4 gW[288];
    __shared__ int    gO[288];
    int t = threadIdx.x;
    int pix0 = blockIdx.x * 32;
    int b = pix0 / HW; int hw = pix0 - b*HW;
    int h = hw / WW;  int w0 = hw - h*WW;

    for (int j = t; j < 288; j += 256) {
        int p = j / 9; int i = j - p*9;
        int pix = pix0 + p;
        float ox = g_off[pix*NOFF + i];
        float oy = g_off[pix*NOFF + 9 + i];
        float px = (float)(h + (i/3)) + ox;
        float py = (float)(w0 + p + (i%3)) + oy;
        float fx = floorf(px), fy = floorf(py);
        int x0 = (int)fx, y0 = (int)fy;
        int x1 = x0 + 1, y1 = y0 + 1;
        x0 = min(max(x0, 0), HH-1); x1 = min(max(x1, 0), HH-1);
        y0 = min(max(y0, 0), WW-1); y1 = min(max(y1, 0), WW-1);
        float pxc = fminf(fmaxf(px, 0.f), (float)(HH-1));
        float pyc = fminf(fmaxf(py, 0.f), (float)(WW-1));
        float wx0 = 1.f + (float)x0 - pxc;
        float wx1 = 1.f - (float)x1 + pxc;
        float wy0 = 1.f + (float)y0 - pyc;
        float wy1 = 1.f - (float)y1 + pyc;
        int base = b * HW;
        gA[j] = make_int4((base + x0*WW + y0)*CH, (base + x1*WW + y1)*CH,
                          (base + x0*WW + y1)*CH, (base + x1*WW + y0)*CH);
        gW[j] = make_float4(wx0*wy0, wx1*wy1, wx0*wy1, wx1*wy0);
        gO[j] = pix*KK + i*64;
    }
    __syncthreads();

    int c4 = (t & 15) * 4;
    int d0 = t >> 4;
#pragma unroll 3
    for (int it = 0; it < 18; it++) {
        int desc = d0 + it*16;
        int4 a = gA[desc]; float4 g = gW[desc];
        float4 v0 = *(const float4*)(in + a.x + c4);
        float4 v1 = *(const float4*)(in + a.y + c4);
        float4 v2 = *(const float4*)(in + a.z + c4);
        float4 v3 = *(const float4*)(in + a.w + c4);
        float4 r;
        r.x = fmaf(g.w, v3.x, fmaf(g.z, v2.x, fmaf(g.y, v1.x, g.x*v0.x)));
        r.y = fmaf(g.w, v3.y, fmaf(g.z, v2.y, fmaf(g.y, v1.y, g.x*v0.y)));
        r.z = fmaf(g.w, v3.z, fmaf(g.z, v2.z, fmaf(g.y, v1.z, g.x*v0.z)));
        r.w = fmaf(g.w, v3.w, fmaf(g.z, v2.w, fmaf(g.y, v1.w, g.x*v0.w)));
        __nv_bfloat162 h01 = __floats2bfloat162_rn(r.x, r.y);
        __nv_bfloat162 h23 = __floats2bfloat162_rn(r.z, r.w);
        float2 f01 = __bfloat1622float2(h01);
        float2 f23 = __bfloat1622float2(h23);
        __nv_bfloat162 l01 = __floats2bfloat162_rn(r.x - f01.x, r.y - f01.y);
        __nv_bfloat162 l23 = __floats2bfloat162_rn(r.z - f23.x, r.w - f23.y);
        unsigned int uh01, uh23, ul01, ul23;
        memcpy(&uh01, &h01, 4); memcpy(&uh23, &h23, 4);
        memcpy(&ul01, &l01, 4); memcpy(&ul23, &l23, 4);
        size_t off = (size_t)gO[desc] + c4;
        *(uint2*)(xgh + off) = make_uint2(uh01, uh23);
        *(uint2*)(xgl + off) = make_uint2(ul01, ul23);
    }
}

// ---------------- mma.sync bf16 GEMM: 128px x 64och, K=576, hi/lo split ----------------
// Warp mapping: 4 px-groups x 2 och-groups (32px x 32och per warp) -> 20% less ldsm traffic.
#define SM_AH   0
#define SM_AL   16384
#define SM_BH   32768
#define SM_BL   40960
#define SM_TOTAL 49152

__global__ __launch_bounds__(256, 2)
void k_gemmtc(const __nv_bfloat16* __restrict__ xh,
              const __nv_bfloat16* __restrict__ xl,
              const __nv_bfloat16* __restrict__ wh,
              const __nv_bfloat16* __restrict__ wl,
              float* __restrict__ yout) {
    extern __shared__ char smem[];
    uint32_t sb = smem_u32(smem);
    int t = threadIdx.x;
    int w = t >> 5, lane = t & 31;
    int pix0 = blockIdx.x * 128;

    // global load mapping: A px = t>>1, half = t&1; B och = t>>2, q = t&3
    int apx = t >> 1, ahalf = t & 1;
    int boch = t >> 2, bq = t & 3;
    const uint4* gah = (const uint4*)(xh + (size_t)(pix0 + apx)*KK) + ahalf*4;
    const uint4* gal = (const uint4*)(xl + (size_t)(pix0 + apx)*KK) + ahalf*4;
    const uint4* gbh = (const uint4*)wh + boch*8 + bq*2;
    const uint4* gbl = (const uint4*)wl + boch*8 + bq*2;
    int asw = apx & 7, bsw = boch & 7;

    // warp tile: pg owns 32 px rows, og owns 32 och
    int pg = w >> 1, og = w & 1;
    int m = lane >> 3, r = lane & 7;
    uint32_t aOff0 = (uint32_t)(32*pg + (m & 1)*8 + r) * 128;   // rowtile 0
    uint32_t aOff1 = aOff0 + 16*128;                             // rowtile 1
    int ac0 = m >> 1;
    int bochp = (m >> 1)*8 + r;
    int bc0 = m & 1;
    int obase = 32*og;

    float acc[2][4][4];
#pragma unroll
    for (int rt = 0; rt < 2; rt++)
#pragma unroll
        for (int n = 0; n < 4; n++)
#pragma unroll
            for (int j = 0; j < 4; j++) acc[rt][n][j] = 0.f;

    uint4 ra[4], rl[4], rbh[2], rbl[2];
#define LOADCH(kc) do { \
        ra[0]=gah[(kc)*8+0]; ra[1]=gah[(kc)*8+1]; ra[2]=gah[(kc)*8+2]; ra[3]=gah[(kc)*8+3]; \
        rl[0]=gal[(kc)*8+0]; rl[1]=gal[(kc)*8+1]; rl[2]=gal[(kc)*8+2]; rl[3]=gal[(kc)*8+3]; \
        rbh[0]=gbh[(kc)*512+0]; rbh[1]=gbh[(kc)*512+1]; \
        rbl[0]=gbl[(kc)*512+0]; rbl[1]=gbl[(kc)*512+1]; \
    } while (0)

    LOADCH(0);
    for (int kc = 0; kc < 9; kc++) {
        __syncthreads();
#pragma unroll
        for (int q = 0; q < 4; q++) {
            uint32_t o = (uint32_t)apx*128 + (uint32_t)(((ahalf*4 + q) ^ asw) << 4);
            sts128(sb + SM_AH + o, ra[q]);
            sts128(sb + SM_AL + o, rl[q]);
        }
#pragma unroll
        for (int q = 0; q < 2; q++) {
            uint32_t o = (uint32_t)boch*128 + (uint32_t)(((bq*2 + q) ^ bsw) << 4);
            sts128(sb + SM_BH + o, rbh[q]);
            sts128(sb + SM_BL + o, rbl[q]);
        }
        __syncthreads();
        if (kc < 8) LOADCH(kc + 1);

#pragma unroll
        for (int kk = 0; kk < 4; kk++) {
            uint32_t ah0[4], al0[4], ah1[4], al1[4];
            uint32_t kx = (uint32_t)(((kk*2 + ac0) ^ r) << 4);
            ldsm4(ah0, sb + SM_AH + aOff0 + kx);
            ldsm4(al0, sb + SM_AL + aOff0 + kx);
            ldsm4(ah1, sb + SM_AH + aOff1 + kx);
            ldsm4(al1, sb + SM_AL + aOff1 + kx);
            uint32_t bco = (uint32_t)(((kk*2 + bc0) ^ r) << 4);
#pragma unroll
            for (int nt = 0; nt < 2; nt++) {
                uint32_t bh[4], bl[4];
                uint32_t bo = (uint32_t)(obase + 16*nt + bochp)*128 + bco;
                ldsm4(bh, sb + SM_BH + bo);
                ldsm4(bl, sb + SM_BL + bo);
                mma16816(acc[0][2*nt],   ah0, bh[0], bh[1]);
                mma16816(acc[0][2*nt+1], ah0, bh[2], bh[3]);
                mma16816(acc[0][2*nt],   ah0, bl[0], bl[1]);
                mma16816(acc[0][2*nt+1], ah0, bl[2], bl[3]);
                mma16816(acc[0][2*nt],   al0, bh[0], bh[1]);
                mma16816(acc[0][2*nt+1], al0, bh[2], bh[3]);
                mma16816(acc[1][2*nt],   ah1, bh[0], bh[1]);
                mma16816(acc[1][2*nt+1], ah1, bh[2], bh[3]);
                mma16816(acc[1][2*nt],   ah1, bl[0], bl[1]);
                mma16816(acc[1][2*nt+1], ah1, bl[2], bl[3]);
                mma16816(acc[1][2*nt],   al1, bh[0], bh[1]);
                mma16816(acc[1][2*nt+1], al1, bh[2], bh[3]);
            }
        }
    }
#undef LOADCH

    // epilogue: stage D (128x64 fp32) in smem, fused BN partials + coalesced store
    __syncthreads();
    float* stg = (float*)smem;             // 32 KB, overlays A tiles
    int g = lane >> 2, tid4 = lane & 3;
#pragma unroll
    for (int rt = 0; rt < 2; rt++) {
#pragma unroll
        for (int n = 0; n < 4; n++) {
            int row0 = 32*pg + 16*rt + g;
            int col = obase + n*8 + tid4*2;
            *(float2*)(stg + row0*64 + col)     = make_float2(acc[rt][n][0], acc[rt][n][1]);
            *(float2*)(stg + (row0+8)*64 + col) = make_float2(acc[rt][n][2], acc[rt][n][3]);
        }
    }
    __syncthreads();

    int och = t & 63, grp = t >> 6;
    float s = 0.f, q = 0.f;
#pragma unroll 4
    for (int j = 0; j < 32; j++) {
        float v = stg[(grp*32 + j)*64 + och];
        s += v;
        q = fmaf(v, v, q);
    }
    float* rs = (float*)(smem + SM_BH);
    float* rq = rs + 256;
    rs[t] = s; rq[t] = q;

    float4* stg4 = (float4*)stg;
    float4* y4 = (float4*)(yout + (size_t)pix0*CH);
#pragma unroll
    for (int j = 0; j < 8; j++) y4[j*256 + t] = stg4[j*256 + t];

    __syncthreads();
    if (t < 64) {
        s = rs[t] + rs[t+64] + rs[t+128] + rs[t+192];
        q = rq[t] + rq[t+64] + rq[t+128] + rq[t+192];
        g_sp[blockIdx.x*64 + t] = s;
        g_qp[blockIdx.x*64 + t] = q;
    }
}

// ---------------- BN finish: reduce 784 partials ----------------
__global__ __launch_bounds__(256) void k_bnfinish(const float* __restrict__ gamma,
                                                  const float* __restrict__ beta) {
    __shared__ float ss[256], sq[256];
    int t = threadIdx.x;
    int c = t & 63, sub = t >> 6;
    float s = 0.f, q = 0.f;
    for (int i = sub; i < GEMMBLKS; i += 4) {
        s += g_sp[i*64 + c];
        q += g_qp[i*64 + c];
    }
    ss[t] = s; sq[t] = q;
    __syncthreads();
    if (t < 64) {
        s = ss[t] + ss[t+64] + ss[t+128] + ss[t+192];
        q = sq[t] + sq[t+64] + sq[t+128] + sq[t+192];
        float inv = 1.f / (float)NPIX;
        float mean = s * inv;
        float var = fmaxf(q * inv - mean*mean, 0.f);
        float r = rsqrtf(var + 1e-5f);
        float a = gamma[t] * r;
        g_ab[t] = a;
        g_ab[64 + t] = beta[t] - mean * a;
    }
}

// ---------------- BN apply + relu, NHWC -> NHWC (stage-1 output) ----------------
__global__ __launch_bounds__(256) void k_bnapply_nhwc(const float* __restrict__ y) {
    int v = blockIdx.x * 256 + threadIdx.x;
    float4 t4 = ((const float4*)y)[v];
    int c = (v & 15) * 4;
    float4 r;
    r.x = fmaxf(fmaf(t4.x, g_ab[c+0], g_ab[64+c+0]), 0.f);
    r.y = fmaxf(fmaf(t4.y, g_ab[c+1], g_ab[64+c+1]), 0.f);
    r.z = fmaxf(fmaf(t4.z, g_ab[c+2], g_ab[64+c+2]), 0.f);
    r.w = fmaxf(fmaf(t4.w, g_ab[c+3], g_ab[64+c+3]), 0.f);
    ((float4*)g_y1n)[v] = r;
}

// ---------------- BN apply + relu + NHWC -> NCHW (final output) ----------------
__global__ __launch_bounds__(256) void k_bnapply_nchw(const float* __restrict__ y,
                                                      float* __restrict__ out) {
    __shared__ float tile[64*33];
    int t = threadIdx.x;
    int pix0 = blockIdx.x * 32;
    int b = pix0 / HW, hw0 = pix0 - b*HW;
    int c = t & 63, q = t >> 6;
    float a = g_ab[c], bb = g_ab[64 + c];
#pragma unroll
    for (int j = 0; j < 8; j++) {
        int p = q*8 + j;
        float v = y[(pix0 + p)*CH + c];
        tile[c*33 + p] = fmaxf(fmaf(v, a, bb), 0.f);
    }
    __syncthreads();
    int p2 = t & 31, cq = t >> 5;
#pragma unroll
    for (int j = 0; j < 8; j++) {
        int cc = cq*8 + j;
        out[(b*CH + cc)*HW + hw0 + p2] = tile[cc*33 + p2];
    }
}

// ---------------- launch ----------------
extern "C" void kernel_launch(void* const* d_in, const int* in_sizes, int n_in,
                              void* d_out, int out_size) {
    const float* x      = (const float*)d_in[0];
    const float* woff1  = (const float*)d_in[1];
    const float* boff1  = (const float*)d_in[2];
    const float* wconv1 = (const float*)d_in[3];
    const float* gamma1 = (const float*)d_in[4];
    const float* beta1  = (const float*)d_in[5];
    const float* woff2  = (const float*)d_in[6];
    const float* boff2  = (const float*)d_in[7];
    const float* wconv2 = (const float*)d_in[8];
    const float* gamma2 = (const float*)d_in[9];
    const float* beta2  = (const float*)d_in[10];
    float* out = (float*)d_out;

    float *p_xh, *p_y1n, *p_yraw;
    __nv_bfloat16 *p_xgh, *p_xgl, *p_wh1, *p_wl1, *p_wh2, *p_wl2;
    cudaGetSymbolAddress((void**)&p_xh,   g_xh);
    cudaGetSymbolAddress((void**)&p_y1n,  g_y1n);
    cudaGetSymbolAddress((void**)&p_yraw, g_yraw);
    cudaGetSymbolAddress((void**)&p_xgh,  g_xgh);
    cudaGetSymbolAddress((void**)&p_xgl,  g_xgl);
    cudaGetSymbolAddress((void**)&p_wh1,  g_wh1);
    cudaGetSymbolAddress((void**)&p_wl1,  g_wl1);
    cudaGetSymbolAddress((void**)&p_wh2,  g_wh2);
    cudaGetSymbolAddress((void**)&p_wl2,  g_wl2);

    cudaFuncSetAttribute(k_offconv, cudaFuncAttributeMaxDynamicSharedMemorySize, OFF_SMEM);
    cudaFuncSetAttribute(k_gemmtc,  cudaFuncAttributeMaxDynamicSharedMemorySize, SM_TOTAL);

    // stage 1  (k_offconv is launch 4 -> ncu capture slot this round)
    k_nchw2nhwc<<<dim3(HW/32, 2, BATCH), dim3(32, 8)>>>(x);                    // 1
    k_prepw<<<144, 256>>>(wconv1, p_wh1, p_wl1);                               // 2
    k_prepw<<<144, 256>>>(wconv2, p_wh2, p_wl2);                               // 3
    k_offconv<<<dim3(2, HH, BATCH), 288, OFF_SMEM>>>(p_xh, woff1, boff1);      // 4
    k_gather<<<NPIX/32, 256>>>(p_xh, p_xgh, p_xgl);                            // 5
    k_gemmtc<<<GEMMBLKS, 256, SM_TOTAL>>>(p_xgh, p_xgl, p_wh1, p_wl1, p_yraw); // 6
    k_bnfinish<<<1, 256>>>(gamma1, beta1);                                     // 7
    k_bnapply_nhwc<<<NPIX*CH/4/256, 256>>>(p_yraw);                            // 8

    // stage 2
    k_offconv<<<dim3(2, HH, BATCH), 288, OFF_SMEM>>>(p_y1n, woff2, boff2);     // 9
    k_gather<<<NPIX/32, 256>>>(p_y1n, p_xgh, p_xgl);                           // 10
    k_gemmtc<<<GEMMBLKS, 256, SM_TOTAL>>>(p_xgh, p_xgl, p_wh2, p_wl2, p_yraw); // 11
    k_bnfinish<<<1, 256>>>(gamma2, beta2);                                     // 12
    k_bnapply_nchw<<<NPIX/32, 256>>>(p_yraw, out);                             // 13
}

// round 11
// speedup vs baseline: 1.9239x; 1.3313x over previous
#include <cstdint>
#include <cstring>
#include <cuda_runtime.h>
#include <cuda_bf16.h>

#define BATCH 2
#define CH 64
#define HH 224
#define WW 224
#define HW (HH*WW)           // 50176
#define NPIX (BATCH*HW)      // 100352
#define NOFF 18
#define KK 576               // 64*9
#define GEMMBLKS (NPIX/128)  // 784

typedef unsigned long long ull;

// ---------------- scratch (static device memory; no allocations) ----------------
__device__ float g_xh[NPIX*CH];              // NHWC input of current stage
__device__ float g_off[NPIX*NOFF];           // offsets NHWC
__device__ __nv_bfloat16 g_xgh[(size_t)NPIX*KK];  // gathered samples hi
__device__ __nv_bfloat16 g_xgl[(size_t)NPIX*KK];  // gathered samples lo
__device__ float g_yraw[NPIX*CH];            // pre-BN conv output NHWC
__device__ float g_y1n[NPIX*CH];             // stage-1 normalized output NHWC
__device__ __nv_bfloat16 g_wh1[9*CH*CH];     // conv W hi: [kc][och][c]
__device__ __nv_bfloat16 g_wl1[9*CH*CH];
__device__ __nv_bfloat16 g_wh2[9*CH*CH];
__device__ __nv_bfloat16 g_wl2[9*CH*CH];
__device__ __nv_bfloat16 g_woh1[9*32*CH];    // offset W hi: [tap][och32][c]
__device__ __nv_bfloat16 g_wol1[9*32*CH];
__device__ __nv_bfloat16 g_woh2[9*32*CH];
__device__ __nv_bfloat16 g_wol2[9*32*CH];
__device__ float g_sp[GEMMBLKS*CH];          // partial sums
__device__ float g_qp[GEMMBLKS*CH];          // partial sumsq
__device__ float g_ab[2*CH];                 // per-channel scale a, shift b

__device__ __forceinline__ uint32_t smem_u32(const void* p) {
    uint32_t a;
    asm("{ .reg .u64 t; cvta.to.shared.u64 t, %1; cvt.u32.u64 %0, t; }" : "=r"(a) : "l"(p));
    return a;
}
__device__ __forceinline__ void sts128(uint32_t a, uint4 v) {
    asm volatile("st.shared.v4.b32 [%0], {%1,%2,%3,%4};"
                 :: "r"(a), "r"(v.x), "r"(v.y), "r"(v.z), "r"(v.w) : "memory");
}
__device__ __forceinline__ void sts64(uint32_t a, uint32_t v0, uint32_t v1) {
    asm volatile("st.shared.v2.b32 [%0], {%1,%2};" :: "r"(a), "r"(v0), "r"(v1) : "memory");
}
__device__ __forceinline__ void ldsm4(uint32_t* r, uint32_t addr) {
    asm volatile("ldmatrix.sync.aligned.m8n8.x4.shared.b16 {%0,%1,%2,%3}, [%4];"
                 : "=r"(r[0]), "=r"(r[1]), "=r"(r[2]), "=r"(r[3]) : "r"(addr));
}
__device__ __forceinline__ void mma16816(float* d, const uint32_t* a, uint32_t b0, uint32_t b1) {
    asm volatile(
        "mma.sync.aligned.m16n8k16.row.col.f32.bf16.bf16.f32 "
        "{%0,%1,%2,%3}, {%4,%5,%6,%7}, {%8,%9}, {%0,%1,%2,%3};"
        : "+f"(d[0]), "+f"(d[1]), "+f"(d[2]), "+f"(d[3])
        : "r"(a[0]), "r"(a[1]), "r"(a[2]), "r"(a[3]), "r"(b0), "r"(b1));
}

// ---------------- NCHW -> NHWC transpose ----------------
__global__ __launch_bounds__(256) void k_nchw2nhwc(const float* __restrict__ x) {
    __shared__ float tile[32][33];
    int b = blockIdx.z;
    int s0 = blockIdx.x * 32, c0 = blockIdx.y * 32;
    int tx = threadIdx.x, ty = threadIdx.y;
#pragma unroll
    for (int j = 0; j < 4; j++) {
        int c = c0 + ty + j*8;
        tile[ty + j*8][tx] = x[(b*CH + c)*HW + s0 + tx];
    }
    __syncthreads();
#pragma unroll
    for (int j = 0; j < 4; j++) {
        int s = s0 + ty + j*8;
        g_xh[(b*HW + s)*CH + c0 + tx] = tile[tx][ty + j*8];
    }
}

// ---------------- conv W split prep: Wh[kc][och][cl] + residual ----------------
__global__ void k_prepw(const float* __restrict__ wconv,
                        __nv_bfloat16* __restrict__ wh,
                        __nv_bfloat16* __restrict__ wl) {
    int j = blockIdx.x * 256 + threadIdx.x;   // 144 blocks x 256 = 36864
    int cl = j & 63, och = (j >> 6) & 63, kc = j >> 12;
    float wv = wconv[och*KK + cl*9 + kc];
    __nv_bfloat16 h = __float2bfloat16(wv);
    wh[j] = h;
    wl[j] = __float2bfloat16(wv - __bfloat162float(h));
}

// ---------------- offset W split prep: [tap][och32][c] (och>=18 zero) ----------------
__global__ void k_prepwoff(const float* __restrict__ woff,
                           __nv_bfloat16* __restrict__ wh,
                           __nv_bfloat16* __restrict__ wl) {
    int j = blockIdx.x * 256 + threadIdx.x;   // 72 blocks x 256 = 18432
    int c = j & 63, och = (j >> 6) & 31, tap = j >> 11;
    float wv = 0.f;
    if (och < NOFF) wv = woff[och*KK + c*9 + tap];
    __nv_bfloat16 h = __float2bfloat16(wv);
    wh[j] = h;
    wl[j] = __float2bfloat16(wv - __bfloat162float(h));
}

// ---------------- offset conv as tensor GEMM: 128px x 18och, implicit im2col ----------
// smem: patch hi/lo [kx(3)][w(130)][c(64)] bf16 + B hi/lo [tap(9)][och(32)][c(64)]
// Swizzle key for the patch is the WITHIN-PLANE row (p & 7) — must match the
// ldmatrix load key (arow & 7); keying on the global row (kx*130+p) broke kx=1,2.
#define OG_PH   0
#define OG_PL   49920
#define OG_BH   99840
#define OG_BL   136704
#define OG_SMEM 173568

__global__ __launch_bounds__(256, 1)
void k_offgemm(const float* __restrict__ in,
               const __nv_bfloat16* __restrict__ wh,
               const __nv_bfloat16* __restrict__ wl,
               const float* __restrict__ boff) {
    extern __shared__ char smem[];
    uint32_t sb = smem_u32(smem);
    int t = threadIdx.x;
    int w = t >> 5, lane = t & 31;
    int w0 = blockIdx.x * 128, h = blockIdx.y, b = blockIdx.z;

    // load B (hi/lo) with per-row XOR swizzle: 288 rows x 128B each (key = och&7 = row&7)
    {
        const uint4* g4h = (const uint4*)wh;
        const uint4* g4l = (const uint4*)wl;
        for (int j = t; j < 2304; j += 256) {
            int row = j >> 3, q = j & 7;
            uint32_t o = (uint32_t)row*128 + (uint32_t)((q ^ (row & 7)) << 4);
            sts128(sb + OG_BH + o, g4h[j]);
            sts128(sb + OG_BL + o, g4l[j]);
        }
    }
    // load patch rows h-1..h+1, cols w0-1..w0+128 (zero-padded), fp32 -> bf16 hi/lo
    for (int j = t; j < 6240; j += 256) {       // 3*130 rows x 16 float4
        int row = j >> 4, e = j & 15;
        int kx = row / 130, p = row - kx*130;
        int hr = h - 1 + kx, wc = w0 - 1 + p;
        float4 v = make_float4(0.f, 0.f, 0.f, 0.f);
        if ((unsigned)hr < (unsigned)HH && (unsigned)wc < (unsigned)WW)
            v = *(const float4*)(in + ((size_t)((b*HH + hr)*WW + wc))*CH + e*4);
        __nv_bfloat162 h01 = __floats2bfloat162_rn(v.x, v.y);
        __nv_bfloat162 h23 = __floats2bfloat162_rn(v.z, v.w);
        float2 f01 = __bfloat1622float2(h01);
        float2 f23 = __bfloat1622float2(h23);
        __nv_bfloat162 l01 = __floats2bfloat162_rn(v.x - f01.x, v.y - f01.y);
        __nv_bfloat162 l23 = __floats2bfloat162_rn(v.z - f23.x, v.w - f23.y);
        unsigned int uh01, uh23, ul01, ul23;
        memcpy(&uh01, &h01, 4); memcpy(&uh23, &h23, 4);
        memcpy(&ul01, &l01, 4); memcpy(&ul23, &l23, 4);
        // swizzle key = within-plane row (p & 7), matching the load side
        uint32_t addr = (uint32_t)row*128 + (uint32_t)((((e >> 1) ^ (p & 7)) << 4) + (e & 1)*8);
        sts64(sb + OG_PH + addr, uh01, uh23);
        sts64(sb + OG_PL + addr, ul01, ul23);
    }
    __syncthreads();

    // fragments (identical convention to k_gemmtc, validated)
    int m = lane >> 3, r = lane & 7;
    int apx = 16*w + (m & 1)*8 + r;      // output pixel row 0..127
    int ac0 = m >> 1;
    int bochp = (m >> 1)*8 + r, bc0 = m & 1;

    float acc[3][4];
#pragma unroll
    for (int n = 0; n < 3; n++)
#pragma unroll
        for (int j = 0; j < 4; j++) acc[n][j] = 0.f;

#pragma unroll
    for (int tap = 0; tap < 9; tap++) {
        int kx = tap / 3, ky = tap - kx*3;
        int arow = apx + ky;                         // shifted patch row (implicit im2col)
        uint32_t aoff = (uint32_t)(kx*16640 + arow*128);
        int akey = arow & 7;
        uint32_t bRow1 = (uint32_t)(tap*32 + bochp)*128;
        uint32_t bRow2 = bRow1 + 16*128;
        int bkey = bochp & 7;
#pragma unroll
        for (int kk = 0; kk < 4; kk++) {
            uint32_t ax = aoff + (uint32_t)(((kk*2 + ac0) ^ akey) << 4);
            uint32_t bx = (uint32_t)(((kk*2 + bc0) ^ bkey) << 4);
            uint32_t ah[4], al[4], b1h[4], b2h[4], b1l[4], b2l[4];
            ldsm4(ah, sb + OG_PH + ax);
            ldsm4(al, sb + OG_PL + ax);
            ldsm4(b1h, sb + OG_BH + bRow1 + bx);
            ldsm4(b2h, sb + OG_BH + bRow2 + bx);
            ldsm4(b1l, sb + OG_BL + bRow1 + bx);
            ldsm4(b2l, sb + OG_BL + bRow2 + bx);
            mma16816(acc[0], ah, b1h[0], b1h[1]);
            mma16816(acc[1], ah, b1h[2], b1h[3]);
            mma16816(acc[2], ah, b2h[0], b2h[1]);
            mma16816(acc[0], ah, b1l[0], b1l[1]);
            mma16816(acc[1], ah, b1l[2], b1l[3]);
            mma16816(acc[2], ah, b2l[0], b2l[1]);
            mma16816(acc[0], al, b1h[0], b1h[1]);
            mma16816(acc[1], al, b1h[2], b1h[3]);
            mma16816(acc[2], al, b2h[0], b2h[1]);
        }
    }

    // epilogue: bias + stage 128x24 fp32, then write g_off[pix][18]
    __syncthreads();
    float* stg = (float*)smem;
    int g = lane >> 2, tid4 = lane & 3;
#pragma unroll
    for (int nt = 0; nt < 3; nt++) {
        int col = nt*8 + tid4*2;
        float b0v = (col     < NOFF) ? boff[col]     : 0.f;
        float b1v = (col + 1 < NOFF) ? boff[col + 1] : 0.f;
        int row0 = 16*w + g;
        stg[row0*24 + col]       = acc[nt][0] + b0v;
        stg[row0*24 + col + 1]   = acc[nt][1] + b1v;
        stg[(row0+8)*24 + col]   = acc[nt][2] + b0v;
        stg[(row0+8)*24 + col+1] = acc[nt][3] + b1v;
    }
    __syncthreads();
    int px = t >> 1, half = t & 1;
    int wpos = w0 + px;
    if (wpos < WW) {
        int base = ((b*HH + h)*WW + wpos)*NOFF + half*9;
#pragma unroll
        for (int i = 0; i < 9; i++)
            g_off[base + i] = stg[px*24 + half*9 + i];
    }
}

// ---------------- gather: bilinear sample -> bf16 hi/lo ----------------
__global__ __launch_bounds__(256) void k_gather(const float* __restrict__ in,
                                                __nv_bfloat16* __restrict__ xgh,
                                                __nv_bfloat16* __restrict__ xgl) {
    __shared__ int4   gA[288];
    __shared__ float4 gW[288];
    __shared__ int    gO[288];
    int t = threadIdx.x;
    int pix0 = blockIdx.x * 32;
    int b = pix0 / HW; int hw = pix0 - b*HW;
    int h = hw / WW;  int w0 = hw - h*WW;

    for (int j = t; j < 288; j += 256) {
        int p = j / 9; int i = j - p*9;
        int pix = pix0 + p;
        float ox = g_off[pix*NOFF + i];
        float oy = g_off[pix*NOFF + 9 + i];
        float px = (float)(h + (i/3)) + ox;
        float py = (float)(w0 + p + (i%3)) + oy;
        float fx = floorf(px), fy = floorf(py);
        int x0 = (int)fx, y0 = (int)fy;
        int x1 = x0 + 1, y1 = y0 + 1;
        x0 = min(max(x0, 0), HH-1); x1 = min(max(x1, 0), HH-1);
        y0 = min(max(y0, 0), WW-1); y1 = min(max(y1, 0), WW-1);
        float pxc = fminf(fmaxf(px, 0.f), (float)(HH-1));
        float pyc = fminf(fmaxf(py, 0.f), (float)(WW-1));
        float wx0 = 1.f + (float)x0 - pxc;
        float wx1 = 1.f - (float)x1 + pxc;
        float wy0 = 1.f + (float)y0 - pyc;
        float wy1 = 1.f - (float)y1 + pyc;
        int base = b * HW;
        gA[j] = make_int4((base + x0*WW + y0)*CH, (base + x1*WW + y1)*CH,
                          (base + x0*WW + y1)*CH, (base + x1*WW + y0)*CH);
        gW[j] = make_float4(wx0*wy0, wx1*wy1, wx0*wy1, wx1*wy0);
        gO[j] = pix*KK + i*64;
    }
    __syncthreads();

    int c4 = (t & 15) * 4;
    int d0 = t >> 4;
#pragma unroll 3
    for (int it = 0; it < 18; it++) {
        int desc = d0 + it*16;
        int4 a = gA[desc]; float4 g = gW[desc];
        float4 v0 = *(const float4*)(in + a.x + c4);
        float4 v1 = *(const float4*)(in + a.y + c4);
        float4 v2 = *(const float4*)(in + a.z + c4);
        float4 v3 = *(const float4*)(in + a.w + c4);
        float4 r;
        r.x = fmaf(g.w, v3.x, fmaf(g.z, v2.x, fmaf(g.y, v1.x, g.x*v0.x)));
        r.y = fmaf(g.w, v3.y, fmaf(g.z, v2.y, fmaf(g.y, v1.y, g.x*v0.y)));
        r.z = fmaf(g.w, v3.z, fmaf(g.z, v2.z, fmaf(g.y, v1.z, g.x*v0.z)));
        r.w = fmaf(g.w, v3.w, fmaf(g.z, v2.w, fmaf(g.y, v1.w, g.x*v0.w)));
        __nv_bfloat162 h01 = __floats2bfloat162_rn(r.x, r.y);
        __nv_bfloat162 h23 = __floats2bfloat162_rn(r.z, r.w);
        float2 f01 = __bfloat1622float2(h01);
        float2 f23 = __bfloat1622float2(h23);
        __nv_bfloat162 l01 = __floats2bfloat162_rn(r.x - f01.x, r.y - f01.y);
        __nv_bfloat162 l23 = __floats2bfloat162_rn(r.z - f23.x, r.w - f23.y);
        unsigned int uh01, uh23, ul01, ul23;
        memcpy(&uh01, &h01, 4); memcpy(&uh23, &h23, 4);
        memcpy(&ul01, &l01, 4); memcpy(&ul23, &l23, 4);
        size_t off = (size_t)gO[desc] + c4;
        *(uint2*)(xgh + off) = make_uint2(uh01, uh23);
        *(uint2*)(xgl + off) = make_uint2(ul01, ul23);
    }
}

// ---------------- mma.sync bf16 GEMM: 128px x 64och, K=576, hi/lo split ----------------
#define SM_AH   0
#define SM_AL   16384
#define SM_BH   32768
#define SM_BL   40960
#define SM_TOTAL 49152

__global__ __launch_bounds__(256, 2)
void k_gemmtc(const __nv_bfloat16* __restrict__ xh,
              const __nv_bfloat16* __restrict__ xl,
              const __nv_bfloat16* __restrict__ wh,
              const __nv_bfloat16* __restrict__ wl,
              float* __restrict__ yout) {
    extern __shared__ char smem[];
    uint32_t sb = smem_u32(smem);
    int t = threadIdx.x;
    int w = t >> 5, lane = t & 31;
    int pix0 = blockIdx.x * 128;

    int apx = t >> 1, ahalf = t & 1;
    int boch = t >> 2, bq = t & 3;
    const uint4* gah = (const uint4*)(xh + (size_t)(pix0 + apx)*KK) + ahalf*4;
    const uint4* gal = (const uint4*)(xl + (size_t)(pix0 + apx)*KK) + ahalf*4;
    const uint4* gbh = (const uint4*)wh + boch*8 + bq*2;
    const uint4* gbl = (const uint4*)wl + boch*8 + bq*2;
    int asw = apx & 7, bsw = boch & 7;

    int pg = w >> 1, og = w & 1;
    int m = lane >> 3, r = lane & 7;
    uint32_t aOff0 = (uint32_t)(32*pg + (m & 1)*8 + r) * 128;
    uint32_t aOff1 = aOff0 + 16*128;
    int ac0 = m >> 1;
    int bochp = (m >> 1)*8 + r;
    int bc0 = m & 1;
    int obase = 32*og;

    float acc[2][4][4];
#pragma unroll
    for (int rt = 0; rt < 2; rt++)
#pragma unroll
        for (int n = 0; n < 4; n++)
#pragma unroll
            for (int j = 0; j < 4; j++) acc[rt][n][j] = 0.f;

    uint4 ra[4], rl[4], rbh[2], rbl[2];
#define LOADCH(kc) do { \
        ra[0]=gah[(kc)*8+0]; ra[1]=gah[(kc)*8+1]; ra[2]=gah[(kc)*8+2]; ra[3]=gah[(kc)*8+3]; \
        rl[0]=gal[(kc)*8+0]; rl[1]=gal[(kc)*8+1]; rl[2]=gal[(kc)*8+2]; rl[3]=gal[(kc)*8+3]; \
        rbh[0]=gbh[(kc)*512+0]; rbh[1]=gbh[(kc)*512+1]; \
        rbl[0]=gbl[(kc)*512+0]; rbl[1]=gbl[(kc)*512+1]; \
    } while (0)

    LOADCH(0);
    for (int kc = 0; kc < 9; kc++) {
        __syncthreads();
#pragma unroll
        for (int q = 0; q < 4; q++) {
            uint32_t o = (uint32_t)apx*128 + (uint32_t)(((ahalf*4 + q) ^ asw) << 4);
            sts128(sb + SM_AH + o, ra[q]);
            sts128(sb + SM_AL + o, rl[q]);
        }
#pragma unroll
        for (int q = 0; q < 2; q++) {
            uint32_t o = (uint32_t)boch*128 + (uint32_t)(((bq*2 + q) ^ bsw) << 4);
            sts128(sb + SM_BH + o, rbh[q]);
            sts128(sb + SM_BL + o, rbl[q]);
        }
        __syncthreads();
        if (kc < 8) LOADCH(kc + 1);

#pragma unroll
        for (int kk = 0; kk < 4; kk++) {
            uint32_t ah0[4], al0[4], ah1[4], al1[4];
            uint32_t kx = (uint32_t)(((kk*2 + ac0) ^ r) << 4);
            ldsm4(ah0, sb + SM_AH + aOff0 + kx);
            ldsm4(al0, sb + SM_AL + aOff0 + kx);
            ldsm4(ah1, sb + SM_AH + aOff1 + kx);
            ldsm4(al1, sb + SM_AL + aOff1 + kx);
            uint32_t bco = (uint32_t)(((kk*2 + bc0) ^ r) << 4);
#pragma unroll
            for (int nt = 0; nt < 2; nt++) {
                uint32_t bh[4], bl[4];
                uint32_t bo = (uint32_t)(obase + 16*nt + bochp)*128 + bco;
                ldsm4(bh, sb + SM_BH + bo);
                ldsm4(bl, sb + SM_BL + bo);
                mma16816(acc[0][2*nt],   ah0, bh[0], bh[1]);
                mma16816(acc[0][2*nt+1], ah0, bh[2], bh[3]);
                mma16816(acc[0][2*nt],   ah0, bl[0], bl[1]);
                mma16816(acc[0][2*nt+1], ah0, bl[2], bl[3]);
                mma16816(acc[0][2*nt],   al0, bh[0], bh[1]);
                mma16816(acc[0][2*nt+1], al0, bh[2], bh[3]);
                mma16816(acc[1][2*nt],   ah1, bh[0], bh[1]);
                mma16816(acc[1][2*nt+1], ah1, bh[2], bh[3]);
                mma16816(acc[1][2*nt],   ah1, bl[0], bl[1]);
                mma16816(acc[1][2*nt+1], ah1, bl[2], bl[3]);
                mma16816(acc[1][2*nt],   al1, bh[0], bh[1]);
                mma16816(acc[1][2*nt+1], al1, bh[2], bh[3]);
            }
        }
    }
#undef LOADCH

    __syncthreads();
    float* stg = (float*)smem;
    int g = lane >> 2, tid4 = lane & 3;
#pragma unroll
    for (int rt = 0; rt < 2; rt++) {
#pragma unroll
        for (int n = 0; n < 4; n++) {
            int row0 = 32*pg + 16*rt + g;
            int col = obase + n*8 + tid4*2;
            *(float2*)(stg + row0*64 + col)     = make_float2(acc[rt][n][0], acc[rt][n][1]);
            *(float2*)(stg + (row0+8)*64 + col) = make_float2(acc[rt][n][2], acc[rt][n][3]);
        }
    }
    __syncthreads();

    int och = t & 63, grp = t >> 6;
    float s = 0.f, q = 0.f;
#pragma unroll 4
    for (int j = 0; j < 32; j++) {
        float v = stg[(grp*32 + j)*64 + och];
        s += v;
        q = fmaf(v, v, q);
    }
    float* rs = (float*)(smem + SM_BH);
    float* rq = rs + 256;
    rs[t] = s; rq[t] = q;

    float4* stg4 = (float4*)stg;
    float4* y4 = (float4*)(yout + (size_t)pix0*CH);
#pragma unroll
    for (int j = 0; j < 8; j++) y4[j*256 + t] = stg4[j*256 + t];

    __syncthreads();
    if (t < 64) {
        s = rs[t] + rs[t+64] + rs[t+128] + rs[t+192];
        q = rq[t] + rq[t+64] + rq[t+128] + rq[t+192];
        g_sp[blockIdx.x*64 + t] = s;
        g_qp[blockIdx.x*64 + t] = q;
    }
}

// ---------------- BN finish: reduce 784 partials ----------------
__global__ __launch_bounds__(256) void k_bnfinish(const float* __restrict__ gamma,
                                                  const float* __restrict__ beta) {
    __shared__ float ss[256], sq[256];
    int t = threadIdx.x;
    int c = t & 63, sub = t >> 6;
    float s = 0.f, q = 0.f;
    for (int i = sub; i < GEMMBLKS; i += 4) {
        s += g_sp[i*64 + c];
        q += g_qp[i*64 + c];
    }
    ss[t] = s; sq[t] = q;
    __syncthreads();
    if (t < 64) {
        s = ss[t] + ss[t+64] + ss[t+128] + ss[t+192];
        q = sq[t] + sq[t+64] + sq[t+128] + sq[t+192];
        float inv = 1.f / (float)NPIX;
        float mean = s * inv;
        float var = fmaxf(q * inv - mean*mean, 0.f);
        float r = rsqrtf(var + 1e-5f);
        float a = gamma[t] * r;
        g_ab[t] = a;
        g_ab[64 + t] = beta[t] - mean * a;
    }
}

// ---------------- BN apply + relu, NHWC -> NHWC (stage-1 output) ----------------
__global__ __launch_bounds__(256) void k_bnapply_nhwc(const float* __restrict__ y) {
    int v = blockIdx.x * 256 + threadIdx.x;
    float4 t4 = ((const float4*)y)[v];
    int c = (v & 15) * 4;
    float4 r;
    r.x = fmaxf(fmaf(t4.x, g_ab[c+0], g_ab[64+c+0]), 0.f);
    r.y = fmaxf(fmaf(t4.y, g_ab[c+1], g_ab[64+c+1]), 0.f);
    r.z = fmaxf(fmaf(t4.z, g_ab[c+2], g_ab[64+c+2]), 0.f);
    r.w = fmaxf(fmaf(t4.w, g_ab[c+3], g_ab[64+c+3]), 0.f);
    ((float4*)g_y1n)[v] = r;
}

// ---------------- BN apply + relu + NHWC -> NCHW (final output) ----------------
__global__ __launch_bounds__(256) void k_bnapply_nchw(const float* __restrict__ y,
                                                      float* __restrict__ out) {
    __shared__ float tile[64*33];
    int t = threadIdx.x;
    int pix0 = blockIdx.x * 32;
    int b = pix0 / HW, hw0 = pix0 - b*HW;
    int c = t & 63, q = t >> 6;
    float a = g_ab[c], bb = g_ab[64 + c];
#pragma unroll
    for (int j = 0; j < 8; j++) {
        int p = q*8 + j;
        float v = y[(pix0 + p)*CH + c];
        tile[c*33 + p] = fmaxf(fmaf(v, a, bb), 0.f);
    }
    __syncthreads();
    int p2 = t & 31, cq = t >> 5;
#pragma unroll
    for (int j = 0; j < 8; j++) {
        int cc = cq*8 + j;
        out[(b*CH + cc)*HW + hw0 + p2] = tile[cc*33 + p2];
    }
}

// ---------------- launch ----------------
extern "C" void kernel_launch(void* const* d_in, const int* in_sizes, int n_in,
                              void* d_out, int out_size) {
    const float* x      = (const float*)d_in[0];
    const float* woff1  = (const float*)d_in[1];
    const float* boff1  = (const float*)d_in[2];
    const float* wconv1 = (const float*)d_in[3];
    const float* gamma1 = (const float*)d_in[4];
    const float* beta1  = (const float*)d_in[5];
    const float* woff2  = (const float*)d_in[6];
    const float* boff2  = (const float*)d_in[7];
    const float* wconv2 = (const float*)d_in[8];
    const float* gamma2 = (const float*)d_in[9];
    const float* beta2  = (const float*)d_in[10];
    float* out = (float*)d_out;

    float *p_xh, *p_y1n, *p_yraw;
    __nv_bfloat16 *p_xgh, *p_xgl, *p_wh1, *p_wl1, *p_wh2, *p_wl2;
    __nv_bfloat16 *p_woh1, *p_wol1, *p_woh2, *p_wol2;
    cudaGetSymbolAddress((void**)&p_xh,   g_xh);
    cudaGetSymbolAddress((void**)&p_y1n,  g_y1n);
    cudaGetSymbolAddress((void**)&p_yraw, g_yraw);
    cudaGetSymbolAddress((void**)&p_xgh,  g_xgh);
    cudaGetSymbolAddress((void**)&p_xgl,  g_xgl);
    cudaGetSymbolAddress((void**)&p_wh1,  g_wh1);
    cudaGetSymbolAddress((void**)&p_wl1,  g_wl1);
    cudaGetSymbolAddress((void**)&p_wh2,  g_wh2);
    cudaGetSymbolAddress((void**)&p_wl2,  g_wl2);
    cudaGetSymbolAddress((void**)&p_woh1, g_woh1);
    cudaGetSymbolAddress((void**)&p_wol1, g_wol1);
    cudaGetSymbolAddress((void**)&p_woh2, g_woh2);
    cudaGetSymbolAddress((void**)&p_wol2, g_wol2);

    cudaFuncSetAttribute(k_offgemm, cudaFuncAttributeMaxDynamicSharedMemorySize, OG_SMEM);
    cudaFuncSetAttribute(k_gemmtc,  cudaFuncAttributeMaxDynamicSharedMemorySize, SM_TOTAL);

    // stage 1  (k_offgemm is launch 4 -> ncu capture slot)
    k_nchw2nhwc<<<dim3(HW/32, 2, BATCH), dim3(32, 8)>>>(x);                          // 1
    k_prepwoff<<<72, 256>>>(woff1, p_woh1, p_wol1);                                  // 2
    k_prepwoff<<<72, 256>>>(woff2, p_woh2, p_wol2);                                  // 3
    k_offgemm<<<dim3(2, HH, BATCH), 256, OG_SMEM>>>(p_xh, p_woh1, p_wol1, boff1);    // 4
    k_prepw<<<144, 256>>>(wconv1, p_wh1, p_wl1);                                     // 5
    k_prepw<<<144, 256>>>(wconv2, p_wh2, p_wl2);                                     // 6
    k_gather<<<NPIX/32, 256>>>(p_xh, p_xgh, p_xgl);                                  // 7
    k_gemmtc<<<GEMMBLKS, 256, SM_TOTAL>>>(p_xgh, p_xgl, p_wh1, p_wl1, p_yraw);       // 8
    k_bnfinish<<<1, 256>>>(gamma1, beta1);                                           // 9
    k_bnapply_nhwc<<<NPIX*CH/4/256, 256>>>(p_yraw);                                  // 10

    // stage 2
    k_offgemm<<<dim3(2, HH, BATCH), 256, OG_SMEM>>>(p_y1n, p_woh2, p_wol2, boff2);   // 11
    k_gather<<<NPIX/32, 256>>>(p_y1n, p_xgh, p_xgl);                                 // 12
    k_gemmtc<<<GEMMBLKS, 256, SM_TOTAL>>>(p_xgh, p_xgl, p_wh2, p_wl2, p_yraw);       // 13
    k_bnfinish<<<1, 256>>>(gamma2, beta2);                                           // 14
    k_bnapply_nchw<<<NPIX/32, 256>>>(p_yraw, out);                                   // 15
}